// round 11
// baseline (speedup 1.0000x reference)
#include <cuda_runtime.h>
#include <cuda_fp16.h>
#include <cstdint>

typedef uint32_t u32;

#define SEQ 8192
#define DM  1024
#define DH  128

#define NEGINF __int_as_float(0xff800000u)

// ---------------- device scratch (no allocs allowed) ----------------
__device__ __align__(16) __half g_Xh[SEQ*DM],  g_Xl[SEQ*DM];
__device__ __align__(16) __half g_Wh[3*DH*DM], g_Wl[3*DH*DM];
__device__ __align__(16) __half g_Qh[SEQ*DH],  g_Ql[SEQ*DH];
__device__ __align__(16) __half g_Kh[SEQ*DH],  g_Kl[SEQ*DH];
__device__ __align__(16) __half g_Vt[DH*SEQ];              // V transposed [dim][seq], single fp16
__device__ float g_Op[4*SEQ*DH];
__device__ float g_mrow[4*SEQ], g_lrow[4*SEQ];

// ---------------- helpers ----------------
__device__ __forceinline__ u32 s2u(const void* p){
    u32 a; asm("{ .reg .u64 t; cvta.to.shared.u64 t, %1; cvt.u32.u64 %0, t; }" : "=r"(a) : "l"(p)); return a;
}
// split two floats into fp16 hi + fp16 residual lo (packed f16x2)
__device__ __forceinline__ void split2(float a, float b, u32 &h, u32 &l){
    __half2 hh = __floats2half2_rn(a, b);
    h = *reinterpret_cast<u32*>(&hh);
    float2 bk = __half22float2(hh);
    __half2 ll = __floats2half2_rn(a - bk.x, b - bk.y);
    l = *reinterpret_cast<u32*>(&ll);
}
__device__ __forceinline__ u32 packh2(float a, float b){
    __half2 hh = __floats2half2_rn(a, b);
    return *reinterpret_cast<u32*>(&hh);
}
__device__ __forceinline__ void ldsm4(u32 a, u32 &r0, u32 &r1, u32 &r2, u32 &r3){
    asm volatile("ldmatrix.sync.aligned.m8n8.x4.shared.b16 {%0,%1,%2,%3}, [%4];"
        : "=r"(r0), "=r"(r1), "=r"(r2), "=r"(r3) : "r"(a));
}
__device__ __forceinline__ void mma16816(float* d, u32 a0, u32 a1, u32 a2, u32 a3, u32 b0, u32 b1){
    asm volatile("mma.sync.aligned.m16n8k16.row.col.f32.f16.f16.f32 "
        "{%0,%1,%2,%3},{%4,%5,%6,%7},{%8,%9},{%0,%1,%2,%3};"
        : "+f"(d[0]), "+f"(d[1]), "+f"(d[2]), "+f"(d[3])
        : "r"(a0), "r"(a1), "r"(a2), "r"(a3), "r"(b0), "r"(b1));
}
__device__ __forceinline__ void cpa16(u32 dst, const void* src){
    asm volatile("cp.async.cg.shared.global [%0], [%1], 16;" :: "r"(dst), "l"(src));
}
#define CPCOMMIT() asm volatile("cp.async.commit_group;" ::: "memory")
#define CPWAIT0()  asm volatile("cp.async.wait_group 0;" ::: "memory")
#define CPWAIT1()  asm volatile("cp.async.wait_group 1;" ::: "memory")

// =====================================================================
// Kernel 0: fp32 -> split fp16 for X and the 3 W matrices
// =====================================================================
__global__ void split_all_kernel(const float4* __restrict__ X,
                                 const float4* __restrict__ Wq,
                                 const float4* __restrict__ Wk,
                                 const float4* __restrict__ Wv)
{
    const int nX4 = SEQ*DM/4, nW4 = DH*DM/4;
    int i = blockIdx.x * blockDim.x + threadIdx.x;
    const float4* src; uint2 *dh, *dl; int off;
    if (i < nX4) {
        src = X; off = i;
        dh = (uint2*)g_Xh; dl = (uint2*)g_Xl;
    } else {
        int k = i - nX4;
        if (k >= 3*nW4) return;
        int mat = k / nW4; off = k - mat*nW4;
        src = (mat==0) ? Wq : (mat==1) ? Wk : Wv;
        dh = (uint2*)(g_Wh + (size_t)mat*DH*DM);
        dl = (uint2*)(g_Wl + (size_t)mat*DH*DM);
    }
    float4 v = src[off];
    u32 h0, l0, h1, l1;
    split2(v.x, v.y, h0, l0);
    split2(v.z, v.w, h1, l1);
    dh[off] = make_uint2(h0, h1);
    dl[off] = make_uint2(l0, l1);
}

// =====================================================================
// Kernel 1: QKV projection, split-fp16 3-term, 2-stream accumulators,
// cp.async 2-stage. grid(128,3): M-tile 64. 256 thr = 8 warps (2m x 4n).
// =====================================================================
#define PSB   144
#define PXH   0
#define PXL   9216
#define PWH   18432
#define PWL   36864
#define PSSZ  55296

__global__ void __launch_bounds__(256,1) proj_kernel()
{
    extern __shared__ __align__(16) char sm[];
    const u32 sb = s2u(sm);

    const int tid = threadIdx.x, lane = tid & 31, wid = tid >> 5;
    const int wm = wid >> 2, wn = wid & 3;       // 2m x 4n
    const int m0 = blockIdx.x * 64, mat = blockIdx.y;
    const __half* __restrict__ Wbh = g_Wh + (size_t)mat*DH*DM;
    const __half* __restrict__ Wbl = g_Wl + (size_t)mat*DH*DM;
    const float scale = (mat==0) ? 0.08838834764831845f : 1.0f;

    const int aRow = lane & 15, aKB = (lane >> 4) << 3;
    const int bRow = (lane & 7) + ((lane >> 4) & 1) * 8, bKB = ((lane >> 3) & 1) << 3;

    auto issue = [&](int kc, int st){
        const u32 base = sb + st*PSSZ;
        #pragma unroll
        for (int it = 0; it < 2; ++it) {
            int idx = tid + it*256;
            int r = idx >> 3, c = idx & 7;
            cpa16(base + PXH + r*PSB + c*16, &g_Xh[(size_t)(m0 + r)*DM + kc*64 + c*8]);
            cpa16(base + PXL + r*PSB + c*16, &g_Xl[(size_t)(m0 + r)*DM + kc*64 + c*8]);
        }
        #pragma unroll
        for (int it = 0; it < 4; ++it) {
            int idx = tid + it*256;
            int r = idx >> 3, c = idx & 7;
            cpa16(base + PWH + r*PSB + c*16, &Wbh[(size_t)r*DM + kc*64 + c*8]);
            cpa16(base + PWL + r*PSB + c*16, &Wbl[(size_t)r*DM + kc*64 + c*8]);
        }
        CPCOMMIT();
    };

    float a1[2][4][4], a2[2][4][4];
    #pragma unroll
    for (int i = 0; i < 2; ++i)
        #pragma unroll
        for (int j = 0; j < 4; ++j)
            #pragma unroll
            for (int c = 0; c < 4; ++c) { a1[i][j][c] = 0.f; a2[i][j][c] = 0.f; }

    issue(0, 0);
    for (int kc = 0; kc < 16; ++kc) {
        const int st = kc & 1;
        const u32 base = sb + st*PSSZ;
        CPWAIT0();
        __syncthreads();
        if (kc + 1 < 16) issue(kc + 1, st ^ 1);

        #pragma unroll
        for (int ks = 0; ks < 4; ++ks) {
            u32 ah[2][4], al[2][4];
            #pragma unroll
            for (int mt = 0; mt < 2; ++mt) {
                u32 qa = base + PXH + (u32)((wm*32 + mt*16 + aRow)*PSB + (ks*16 + aKB)*2);
                ldsm4(qa,             ah[mt][0], ah[mt][1], ah[mt][2], ah[mt][3]);
                ldsm4(qa + (PXL-PXH), al[mt][0], al[mt][1], al[mt][2], al[mt][3]);
            }
            #pragma unroll
            for (int nb = 0; nb < 2; ++nb) {
                u32 bh[4], bl[4];
                u32 ba = base + PWH + (u32)((wn*32 + nb*16 + bRow)*PSB + (ks*16 + bKB)*2);
                ldsm4(ba,             bh[0], bh[1], bh[2], bh[3]);
                ldsm4(ba + (PWL-PWH), bl[0], bl[1], bl[2], bl[3]);
                #pragma unroll
                for (int mt = 0; mt < 2; ++mt) {
                    mma16816(a1[mt][nb*2],   ah[mt][0],ah[mt][1],ah[mt][2],ah[mt][3], bh[0], bh[1]);
                    mma16816(a2[mt][nb*2],   ah[mt][0],ah[mt][1],ah[mt][2],ah[mt][3], bl[0], bl[1]);
                    mma16816(a2[mt][nb*2],   al[mt][0],al[mt][1],al[mt][2],al[mt][3], bh[0], bh[1]);
                    mma16816(a1[mt][nb*2+1], ah[mt][0],ah[mt][1],ah[mt][2],ah[mt][3], bh[2], bh[3]);
                    mma16816(a2[mt][nb*2+1], ah[mt][0],ah[mt][1],ah[mt][2],ah[mt][3], bl[2], bl[3]);
                    mma16816(a2[mt][nb*2+1], al[mt][0],al[mt][1],al[mt][2],al[mt][3], bh[2], bh[3]);
                }
            }
        }
        __syncthreads();
    }

    #pragma unroll
    for (int mt = 0; mt < 2; ++mt) {
        const int r0 = m0 + wm*32 + mt*16 + (lane >> 2);
        const int r1 = r0 + 8;
        #pragma unroll
        for (int nt = 0; nt < 4; ++nt) {
            const int col = wn*32 + nt*8 + (lane & 3)*2;
            float c0 = (a1[mt][nt][0] + a2[mt][nt][0])*scale;
            float c1 = (a1[mt][nt][1] + a2[mt][nt][1])*scale;
            float c2 = (a1[mt][nt][2] + a2[mt][nt][2])*scale;
            float c3 = (a1[mt][nt][3] + a2[mt][nt][3])*scale;
            if (mat < 2) {
                __half* GH = (mat==0) ? g_Qh : g_Kh;
                __half* GL = (mat==0) ? g_Ql : g_Kl;
                u32 h, l;
                split2(c0, c1, h, l);
                *(u32*)&GH[(size_t)r0*DH + col] = h;  *(u32*)&GL[(size_t)r0*DH + col] = l;
                split2(c2, c3, h, l);
                *(u32*)&GH[(size_t)r1*DH + col] = h;  *(u32*)&GL[(size_t)r1*DH + col] = l;
            } else {
                g_Vt[(size_t)(col    )*SEQ + r0] = __float2half_rn(c0);
                g_Vt[(size_t)(col + 1)*SEQ + r0] = __float2half_rn(c1);
                g_Vt[(size_t)(col    )*SEQ + r1] = __float2half_rn(c2);
                g_Vt[(size_t)(col + 1)*SEQ + r1] = __float2half_rn(c3);
            }
        }
    }
}

// =====================================================================
// Kernel 2: causal flash attention. fp16: S 3-term (2 streams),
// P single fp16, V single fp16.
// 256 CTAs x 128 thr (4 warps), 88KB smem -> 2 CTAs/SM.
// NEW: phase-shifted K/V prefetch in separate cp.async commit groups —
// K(j+1) issued after S(j) reads K (hides under softmax+PV), V(j+1)
// issued after PV(j) reads V (hides under next S). Same smem buffers.
// CTA (qq,pp): KV-quarter qq of 64-row q-tiles pp & 127-pp.
// =====================================================================
#define ASB   272            // Q/K row stride bytes (128 kcols fp16 + pad)
#define VSB   144            // V row stride bytes (64 key cols fp16 + pad)
#define AQH   0
#define AQL   17408
#define AKH   34816
#define AKL   52224
#define AVH   69632
#define ASM_T 88064          // total per CTA

__global__ void __launch_bounds__(128,2) attn_kernel()
{
    extern __shared__ __align__(16) char sm[];
    const u32 sb = s2u(sm);

    const int tid = threadIdx.x, lane = tid & 31, w = tid >> 5;
    const int qq = blockIdx.x >> 6;   // kv quarter 0..3
    const int pp = blockIdx.x & 63;   // pair id 0..63

    const int aRow = lane & 15, aKB = (lane >> 4) << 3;
    const int bRow = (lane & 7) + ((lane >> 4) & 1) * 8, bKB = ((lane >> 3) & 1) << 3;
    const int rl0 = w*16 + (lane >> 2);   // local q-row (0..63)
    const int rl1 = rl0 + 8;

    auto issueK = [&](int j){
        #pragma unroll
        for (int it = 0; it < 8; ++it) {     // K: 64 rows x 16 chunks, hi+lo (1024 xfers)
            int idx = tid + it*128;
            int r = idx >> 4, c = idx & 15;
            cpa16(sb + AKH + r*ASB + c*16, &g_Kh[(size_t)(j*64 + r)*DH + c*8]);
            cpa16(sb + AKL + r*ASB + c*16, &g_Kl[(size_t)(j*64 + r)*DH + c*8]);
        }
        CPCOMMIT();
    };
    auto issueV = [&](int j){
        #pragma unroll
        for (int it = 0; it < 8; ++it) {     // V: 128 dim-rows x 8 chunks (1024 xfers)
            int idx = tid + it*128;
            int r = idx >> 3, c = idx & 7;
            cpa16(sb + AVH + r*VSB + c*16, &g_Vt[(size_t)r*SEQ + j*64 + c*8]);
        }
        CPCOMMIT();
    };

    #pragma unroll 1
    for (int u = 0; u < 2; ++u) {
        const int i  = u ? (127 - pp) : pp;   // 64-row q-tile
        const int Tt = i + 1;                 // 64-key subtiles
        const int Tq = (Tt + 3) >> 2;
        const int j0 = qq * Tq;
        const int j1 = (j0 + Tq < Tt) ? (j0 + Tq) : Tt;
        const int brow = qq*SEQ + i*64;

        if (j0 >= j1) {
            if (tid < 64) { g_mrow[brow + tid] = NEGINF; g_lrow[brow + tid] = 0.f; }
            continue;
        }

        __syncthreads();   // prior unit done reading Q/K/V smem; groups drained
        // Q (hi+lo) goes in the same commit group as K(j0)
        #pragma unroll
        for (int it = 0; it < 8; ++it) {
            int idx = tid + it*128;
            int r = idx >> 4, c = idx & 15;
            cpa16(sb + AQH + r*ASB + c*16, &g_Qh[(size_t)(i*64 + r)*DH + c*8]);
            cpa16(sb + AQL + r*ASB + c*16, &g_Ql[(size_t)(i*64 + r)*DH + c*8]);
        }
        issueK(j0);        // group: {Q, K(j0)}
        issueV(j0);        // group: {V(j0)}

        float o[16][4];
        #pragma unroll
        for (int nt = 0; nt < 16; ++nt)
            #pragma unroll
            for (int c = 0; c < 4; ++c) o[nt][c] = 0.f;
        float m0r = NEGINF, m1r = NEGINF, l0 = 0.f, l1 = 0.f;

        #pragma unroll 1
        for (int j = j0; j < j1; ++j) {
            const bool hn = (j + 1 < j1);

            // pending: {K(j) [+Q if first], V(j)}; K older -> wait_group 1
            CPWAIT1();
            __syncthreads();               // K(j) (+Q) visible to all warps

            // ---- S = Q K^T, 2 accumulation streams ----
            float s1[8][4], s2[8][4];
            #pragma unroll
            for (int nt = 0; nt < 8; ++nt)
                #pragma unroll
                for (int c = 0; c < 4; ++c) { s1[nt][c] = 0.f; s2[nt][c] = 0.f; }

            #pragma unroll
            for (int ks = 0; ks < 8; ++ks) {
                u32 qh[4], ql[4];
                u32 qa = sb + AQH + (u32)((w*16 + aRow)*ASB + (ks*16 + aKB)*2);
                ldsm4(qa,             qh[0], qh[1], qh[2], qh[3]);
                ldsm4(qa + (AQL-AQH), ql[0], ql[1], ql[2], ql[3]);
                #pragma unroll
                for (int nbp = 0; nbp < 4; ++nbp) {
                    u32 kh[4], kl[4];
                    u32 ba = sb + AKH + (u32)((nbp*16 + bRow)*ASB + (ks*16 + bKB)*2);
                    ldsm4(ba,             kh[0], kh[1], kh[2], kh[3]);
                    ldsm4(ba + (AKL-AKH), kl[0], kl[1], kl[2], kl[3]);
                    mma16816(s1[nbp*2],   qh[0],qh[1],qh[2],qh[3], kh[0], kh[1]);
                    mma16816(s2[nbp*2],   qh[0],qh[1],qh[2],qh[3], kl[0], kl[1]);
                    mma16816(s2[nbp*2],   ql[0],ql[1],ql[2],ql[3], kh[0], kh[1]);
                    mma16816(s1[nbp*2+1], qh[0],qh[1],qh[2],qh[3], kh[2], kh[3]);
                    mma16816(s2[nbp*2+1], qh[0],qh[1],qh[2],qh[3], kl[2], kl[3]);
                    mma16816(s2[nbp*2+1], ql[0],ql[1],ql[2],ql[3], kh[2], kh[3]);
                }
            }
            __syncthreads();               // all warps done reading K(j)
            if (hn) issueK(j + 1);         // prefetch K under softmax+PV

            #pragma unroll
            for (int nt = 0; nt < 8; ++nt)
                #pragma unroll
                for (int c = 0; c < 4; ++c) s1[nt][c] += s2[nt][c];

            // ---- causal mask (diagonal subtile only) ----
            if (j == i) {
                const int gr0 = i*64 + rl0, gr1 = i*64 + rl1;
                #pragma unroll
                for (int nt = 0; nt < 8; ++nt) {
                    int gc = j*64 + nt*8 + (lane & 3)*2;
                    if (gc     > gr0) s1[nt][0] = NEGINF;
                    if (gc + 1 > gr0) s1[nt][1] = NEGINF;
                    if (gc     > gr1) s1[nt][2] = NEGINF;
                    if (gc + 1 > gr1) s1[nt][3] = NEGINF;
                }
            }

            // ---- online softmax (quad-local rows) ----
            float mx0 = NEGINF, mx1 = NEGINF;
            #pragma unroll
            for (int nt = 0; nt < 8; ++nt) {
                mx0 = fmaxf(mx0, fmaxf(s1[nt][0], s1[nt][1]));
                mx1 = fmaxf(mx1, fmaxf(s1[nt][2], s1[nt][3]));
            }
            mx0 = fmaxf(mx0, __shfl_xor_sync(0xffffffffu, mx0, 1));
            mx0 = fmaxf(mx0, __shfl_xor_sync(0xffffffffu, mx0, 2));
            mx1 = fmaxf(mx1, __shfl_xor_sync(0xffffffffu, mx1, 1));
            mx1 = fmaxf(mx1, __shfl_xor_sync(0xffffffffu, mx1, 2));

            float mn0 = fmaxf(m0r, mx0), mn1 = fmaxf(m1r, mx1);
            float al0 = __expf(m0r - mn0), al1 = __expf(m1r - mn1);

            u32 p2[16];
            float sum0 = 0.f, sum1 = 0.f;
            #pragma unroll
            for (int nt = 0; nt < 8; ++nt) {
                float p0  = __expf(s1[nt][0] - mn0);
                float p1  = __expf(s1[nt][1] - mn0);
                float p2f = __expf(s1[nt][2] - mn1);
                float p3  = __expf(s1[nt][3] - mn1);
                sum0 += p0 + p1;  sum1 += p2f + p3;
                p2[nt*2]   = packh2(p0, p1);
                p2[nt*2+1] = packh2(p2f, p3);
            }
            sum0 += __shfl_xor_sync(0xffffffffu, sum0, 1);
            sum0 += __shfl_xor_sync(0xffffffffu, sum0, 2);
            sum1 += __shfl_xor_sync(0xffffffffu, sum1, 1);
            sum1 += __shfl_xor_sync(0xffffffffu, sum1, 2);

            l0 = l0*al0 + sum0;  l1 = l1*al1 + sum1;
            m0r = mn0;  m1r = mn1;

            bool need = (al0 < 1.f) || (al1 < 1.f);
            if (__ballot_sync(0xffffffffu, need)) {
                #pragma unroll
                for (int nt = 0; nt < 16; ++nt) {
                    o[nt][0] *= al0;  o[nt][1] *= al0;
                    o[nt][2] *= al1;  o[nt][3] *= al1;
                }
            }

            // pending: {V(j) [, K(j+1)]}; V older
            if (hn) CPWAIT1(); else CPWAIT0();
            __syncthreads();               // V(j) visible

            // ---- O += P(fp16) * V(fp16) ----
            #pragma unroll
            for (int t = 0; t < 4; ++t) {
                #pragma unroll
                for (int nbp = 0; nbp < 8; ++nbp) {
                    u32 vh[4];
                    u32 ba = sb + AVH + (u32)((nbp*16 + bRow)*VSB + (t*16 + bKB)*2);
                    ldsm4(ba, vh[0], vh[1], vh[2], vh[3]);
                    mma16816(o[nbp*2],   p2[4*t],p2[4*t+1],p2[4*t+2],p2[4*t+3], vh[0], vh[1]);
                    mma16816(o[nbp*2+1], p2[4*t],p2[4*t+1],p2[4*t+2],p2[4*t+3], vh[2], vh[3]);
                }
            }
            __syncthreads();               // all warps done reading V(j)
            if (hn) issueV(j + 1);         // prefetch V under next S
        }

        // ---- store partials ----
        const int gr0 = brow + rl0, gr1 = brow + rl1;
        #pragma unroll
        for (int nt = 0; nt < 16; ++nt) {
            const int col = nt*8 + (lane & 3)*2;
            *(float2*)&g_Op[(size_t)gr0*DH + col] = make_float2(o[nt][0], o[nt][1]);
            *(float2*)&g_Op[(size_t)gr1*DH + col] = make_float2(o[nt][2], o[nt][3]);
        }
        if ((lane & 3) == 0) {
            g_mrow[gr0] = m0r;  g_lrow[gr0] = l0;
            g_mrow[gr1] = m1r;  g_lrow[gr1] = l1;
        }
    }
}

// =====================================================================
// Kernel 3: merge 4 KV-quarter partials per row (LSE combine), float4.
// =====================================================================
__global__ void merge_kernel(float* __restrict__ Out)
{
    const int t = threadIdx.x;
    const int row = blockIdx.x*4 + (t >> 5);
    const int c = (t & 31)*4;

    float mv[4], lv[4];
    float mmax = NEGINF;
    #pragma unroll
    for (int q = 0; q < 4; ++q) {
        mv[q] = g_mrow[q*SEQ + row];
        lv[q] = g_lrow[q*SEQ + row];
        if (lv[q] > 0.f) mmax = fmaxf(mmax, mv[q]);
    }
    float4 acc = make_float4(0.f, 0.f, 0.f, 0.f);
    float ws = 0.f;
    #pragma unroll
    for (int q = 0; q < 4; ++q) {
        if (lv[q] > 0.f) {
            float wgt = __expf(mv[q] - mmax);
            float4 v = *(const float4*)&g_Op[((size_t)q*SEQ + row)*DH + c];
            acc.x += wgt*v.x; acc.y += wgt*v.y; acc.z += wgt*v.z; acc.w += wgt*v.w;
            ws += wgt * lv[q];
        }
    }
    float inv = 1.0f / ws;
    *(float4*)&Out[(size_t)row*DH + c] =
        make_float4(acc.x*inv, acc.y*inv, acc.z*inv, acc.w*inv);
}

// =====================================================================
extern "C" void kernel_launch(void* const* d_in, const int* in_sizes, int n_in,
                              void* d_out, int out_size)
{
    (void)in_sizes; (void)n_in; (void)out_size;
    const float* X  = (const float*)d_in[0];
    const float* Wq = (const float*)d_in[1];
    const float* Wk = (const float*)d_in[2];
    const float* Wv = (const float*)d_in[3];

    const int nTot = SEQ*DM/4 + 3*DH*DM/4;
    split_all_kernel<<<(nTot + 255)/256, 256>>>(
        (const float4*)X, (const float4*)Wq, (const float4*)Wk, (const float4*)Wv);

    const int PSM = 2*PSSZ;                 // 110592
    cudaFuncSetAttribute(proj_kernel, cudaFuncAttributeMaxDynamicSharedMemorySize, PSM);
    cudaFuncSetAttribute(attn_kernel, cudaFuncAttributeMaxDynamicSharedMemorySize, ASM_T);

    proj_kernel<<<dim3(128, 3), 256, PSM>>>();
    attn_kernel<<<256, 128, ASM_T>>>();
    merge_kernel<<<SEQ/4, 128>>>((float*)d_out);
}

// round 12
// speedup vs baseline: 1.3386x; 1.3386x over previous
#include <cuda_runtime.h>
#include <cuda_fp16.h>
#include <cstdint>

typedef uint32_t u32;

#define SEQ 8192
#define DM  1024
#define DH  128
#define NPAR 6

#define NEGINF __int_as_float(0xff800000u)

// ---------------- device scratch (no allocs allowed) ----------------
__device__ __align__(16) __half g_Xh[SEQ*DM],  g_Xl[SEQ*DM];
__device__ __align__(16) __half g_Wh[3*DH*DM], g_Wl[3*DH*DM];
__device__ __align__(16) __half g_Q[SEQ*DH];               // scaled by log2e/sqrt(dk)
__device__ __align__(16) __half g_K[SEQ*DH];
__device__ __align__(16) __half g_Vt[DH*SEQ];              // V transposed [dim][seq]
__device__ float g_Op[NPAR*SEQ*DH];
__device__ float g_mrow[NPAR*SEQ], g_lrow[NPAR*SEQ];

// ---------------- helpers ----------------
__device__ __forceinline__ u32 s2u(const void* p){
    u32 a; asm("{ .reg .u64 t; cvta.to.shared.u64 t, %1; cvt.u32.u64 %0, t; }" : "=r"(a) : "l"(p)); return a;
}
__device__ __forceinline__ void split2(float a, float b, u32 &h, u32 &l){
    __half2 hh = __floats2half2_rn(a, b);
    h = *reinterpret_cast<u32*>(&hh);
    float2 bk = __half22float2(hh);
    __half2 ll = __floats2half2_rn(a - bk.x, b - bk.y);
    l = *reinterpret_cast<u32*>(&ll);
}
__device__ __forceinline__ u32 packh2(float a, float b){
    __half2 hh = __floats2half2_rn(a, b);
    return *reinterpret_cast<u32*>(&hh);
}
__device__ __forceinline__ float ex2f(float x){
    float r; asm("ex2.approx.ftz.f32 %0, %1;" : "=f"(r) : "f"(x)); return r;
}
__device__ __forceinline__ void ldsm4(u32 a, u32 &r0, u32 &r1, u32 &r2, u32 &r3){
    asm volatile("ldmatrix.sync.aligned.m8n8.x4.shared.b16 {%0,%1,%2,%3}, [%4];"
        : "=r"(r0), "=r"(r1), "=r"(r2), "=r"(r3) : "r"(a));
}
__device__ __forceinline__ void mma16816(float* d, u32 a0, u32 a1, u32 a2, u32 a3, u32 b0, u32 b1){
    asm volatile("mma.sync.aligned.m16n8k16.row.col.f32.f16.f16.f32 "
        "{%0,%1,%2,%3},{%4,%5,%6,%7},{%8,%9},{%0,%1,%2,%3};"
        : "+f"(d[0]), "+f"(d[1]), "+f"(d[2]), "+f"(d[3])
        : "r"(a0), "r"(a1), "r"(a2), "r"(a3), "r"(b0), "r"(b1));
}
__device__ __forceinline__ void cpa16(u32 dst, const void* src){
    asm volatile("cp.async.cg.shared.global [%0], [%1], 16;" :: "r"(dst), "l"(src));
}
#define CPCOMMIT() asm volatile("cp.async.commit_group;" ::: "memory")
#define CPWAIT0()  asm volatile("cp.async.wait_group 0;" ::: "memory")

// =====================================================================
// Kernel 0: fp32 -> split fp16 for X and the 3 W matrices
// =====================================================================
__global__ void split_all_kernel(const float4* __restrict__ X,
                                 const float4* __restrict__ Wq,
                                 const float4* __restrict__ Wk,
                                 const float4* __restrict__ Wv)
{
    const int nX4 = SEQ*DM/4, nW4 = DH*DM/4;
    int i = blockIdx.x * blockDim.x + threadIdx.x;
    const float4* src; uint2 *dh, *dl; int off;
    if (i < nX4) {
        src = X; off = i;
        dh = (uint2*)g_Xh; dl = (uint2*)g_Xl;
    } else {
        int k = i - nX4;
        if (k >= 3*nW4) return;
        int mat = k / nW4; off = k - mat*nW4;
        src = (mat==0) ? Wq : (mat==1) ? Wk : Wv;
        dh = (uint2*)(g_Wh + (size_t)mat*DH*DM);
        dl = (uint2*)(g_Wl + (size_t)mat*DH*DM);
    }
    float4 v = src[off];
    u32 h0, l0, h1, l1;
    split2(v.x, v.y, h0, l0);
    split2(v.z, v.w, h1, l1);
    dh[off] = make_uint2(h0, h1);
    dl[off] = make_uint2(l0, l1);
}

// =====================================================================
// Kernel 1: QKV projection, split-fp16 3-term, 2-stream accumulators,
// cp.async 2-stage. grid(128,3): M-tile 64. 256 thr = 8 warps (2m x 4n).
// Q output folded-scaled by log2e/sqrt(dk); Q/K stored single fp16;
// V stored transposed single fp16.
// =====================================================================
#define PSB   144
#define PXH   0
#define PXL   9216
#define PWH   18432
#define PWL   36864
#define PSSZ  55296

__global__ void __launch_bounds__(256,1) proj_kernel()
{
    extern __shared__ __align__(16) char sm[];
    const u32 sb = s2u(sm);

    const int tid = threadIdx.x, lane = tid & 31, wid = tid >> 5;
    const int wm = wid >> 2, wn = wid & 3;       // 2m x 4n
    const int m0 = blockIdx.x * 64, mat = blockIdx.y;
    const __half* __restrict__ Wbh = g_Wh + (size_t)mat*DH*DM;
    const __half* __restrict__ Wbl = g_Wl + (size_t)mat*DH*DM;
    // Q scale = log2(e)/sqrt(128); softmax runs in log2 domain
    const float scale = (mat==0) ? 0.1275174436f : 1.0f;

    const int aRow = lane & 15, aKB = (lane >> 4) << 3;
    const int bRow = (lane & 7) + ((lane >> 4) & 1) * 8, bKB = ((lane >> 3) & 1) << 3;

    auto issue = [&](int kc, int st){
        const u32 base = sb + st*PSSZ;
        #pragma unroll
        for (int it = 0; it < 2; ++it) {
            int idx = tid + it*256;
            int r = idx >> 3, c = idx & 7;
            cpa16(base + PXH + r*PSB + c*16, &g_Xh[(size_t)(m0 + r)*DM + kc*64 + c*8]);
            cpa16(base + PXL + r*PSB + c*16, &g_Xl[(size_t)(m0 + r)*DM + kc*64 + c*8]);
        }
        #pragma unroll
        for (int it = 0; it < 4; ++it) {
            int idx = tid + it*256;
            int r = idx >> 3, c = idx & 7;
            cpa16(base + PWH + r*PSB + c*16, &Wbh[(size_t)r*DM + kc*64 + c*8]);
            cpa16(base + PWL + r*PSB + c*16, &Wbl[(size_t)r*DM + kc*64 + c*8]);
        }
        CPCOMMIT();
    };

    float a1[2][4][4], a2[2][4][4];
    #pragma unroll
    for (int i = 0; i < 2; ++i)
        #pragma unroll
        for (int j = 0; j < 4; ++j)
            #pragma unroll
            for (int c = 0; c < 4; ++c) { a1[i][j][c] = 0.f; a2[i][j][c] = 0.f; }

    issue(0, 0);
    for (int kc = 0; kc < 16; ++kc) {
        const int st = kc & 1;
        const u32 base = sb + st*PSSZ;
        CPWAIT0();
        __syncthreads();
        if (kc + 1 < 16) issue(kc + 1, st ^ 1);

        #pragma unroll
        for (int ks = 0; ks < 4; ++ks) {
            u32 ah[2][4], al[2][4];
            #pragma unroll
            for (int mt = 0; mt < 2; ++mt) {
                u32 qa = base + PXH + (u32)((wm*32 + mt*16 + aRow)*PSB + (ks*16 + aKB)*2);
                ldsm4(qa,             ah[mt][0], ah[mt][1], ah[mt][2], ah[mt][3]);
                ldsm4(qa + (PXL-PXH), al[mt][0], al[mt][1], al[mt][2], al[mt][3]);
            }
            #pragma unroll
            for (int nb = 0; nb < 2; ++nb) {
                u32 bh[4], bl[4];
                u32 ba = base + PWH + (u32)((wn*32 + nb*16 + bRow)*PSB + (ks*16 + bKB)*2);
                ldsm4(ba,             bh[0], bh[1], bh[2], bh[3]);
                ldsm4(ba + (PWL-PWH), bl[0], bl[1], bl[2], bl[3]);
                #pragma unroll
                for (int mt = 0; mt < 2; ++mt) {
                    mma16816(a1[mt][nb*2],   ah[mt][0],ah[mt][1],ah[mt][2],ah[mt][3], bh[0], bh[1]);
                    mma16816(a2[mt][nb*2],   ah[mt][0],ah[mt][1],ah[mt][2],ah[mt][3], bl[0], bl[1]);
                    mma16816(a2[mt][nb*2],   al[mt][0],al[mt][1],al[mt][2],al[mt][3], bh[0], bh[1]);
                    mma16816(a1[mt][nb*2+1], ah[mt][0],ah[mt][1],ah[mt][2],ah[mt][3], bh[2], bh[3]);
                    mma16816(a2[mt][nb*2+1], ah[mt][0],ah[mt][1],ah[mt][2],ah[mt][3], bl[2], bl[3]);
                    mma16816(a2[mt][nb*2+1], al[mt][0],al[mt][1],al[mt][2],al[mt][3], bh[2], bh[3]);
                }
            }
        }
        __syncthreads();
    }

    #pragma unroll
    for (int mt = 0; mt < 2; ++mt) {
        const int r0 = m0 + wm*32 + mt*16 + (lane >> 2);
        const int r1 = r0 + 8;
        #pragma unroll
        for (int nt = 0; nt < 4; ++nt) {
            const int col = wn*32 + nt*8 + (lane & 3)*2;
            float c0 = (a1[mt][nt][0] + a2[mt][nt][0])*scale;
            float c1 = (a1[mt][nt][1] + a2[mt][nt][1])*scale;
            float c2 = (a1[mt][nt][2] + a2[mt][nt][2])*scale;
            float c3 = (a1[mt][nt][3] + a2[mt][nt][3])*scale;
            if (mat < 2) {
                __half* G = (mat==0) ? g_Q : g_K;
                *(u32*)&G[(size_t)r0*DH + col] = packh2(c0, c1);
                *(u32*)&G[(size_t)r1*DH + col] = packh2(c2, c3);
            } else {
                g_Vt[(size_t)(col    )*SEQ + r0] = __float2half_rn(c0);
                g_Vt[(size_t)(col + 1)*SEQ + r0] = __float2half_rn(c1);
                g_Vt[(size_t)(col    )*SEQ + r1] = __float2half_rn(c2);
                g_Vt[(size_t)(col + 1)*SEQ + r1] = __float2half_rn(c3);
            }
        }
    }
}

// =====================================================================
// Kernel 2: causal flash attention, all-fp16 operands (error-budgeted),
// log2-domain softmax, l computed by the PV MMA via a ones-block in V.
// 384 CTAs x 128 thr, 55.5KB smem -> 3 CTAs/SM (3-way cross-CTA overlap).
// CTA (qq,pp): KV-sixth qq of 64-row q-tiles pp & 127-pp.
// =====================================================================
#define ASB   272            // Q/K row stride bytes (128 kcols fp16 + pad)
#define VSB   144            // V row stride bytes (64 key cols fp16 + pad)
#define AQ    0              // Q: 64 x 272 = 17408
#define AK    17408          // K: 64 x 272 = 17408
#define AV    34816          // V: 144 x 144 = 20736 (rows 128..143 = ones)
#define ASM_T 55552

__global__ void __launch_bounds__(128,3) attn_kernel()
{
    extern __shared__ __align__(16) char sm[];
    const u32 sb = s2u(sm);

    const int tid = threadIdx.x, lane = tid & 31, w = tid >> 5;
    const int qq = blockIdx.x >> 6;   // kv sixth 0..5
    const int pp = blockIdx.x & 63;   // pair id 0..63

    const int aRow = lane & 15, aKB = (lane >> 4) << 3;
    const int bRow = (lane & 7) + ((lane >> 4) & 1) * 8, bKB = ((lane >> 3) & 1) << 3;
    const int rl0 = w*16 + (lane >> 2);   // local q-row (0..63)
    const int rl1 = rl0 + 8;

    auto issueKV = [&](int j){
        #pragma unroll
        for (int it = 0; it < 8; ++it) {     // K: 64 rows x 16 chunks
            int idx = tid + it*128;
            int r = idx >> 4, c = idx & 15;
            cpa16(sb + AK + r*ASB + c*16, &g_K[(size_t)(j*64 + r)*DH + c*8]);
        }
        #pragma unroll
        for (int it = 0; it < 8; ++it) {     // V: 128 dim-rows x 8 chunks
            int idx = tid + it*128;
            int r = idx >> 3, c = idx & 7;
            cpa16(sb + AV + r*VSB + c*16, &g_Vt[(size_t)r*SEQ + j*64 + c*8]);
        }
        CPCOMMIT();
    };

    #pragma unroll 1
    for (int u = 0; u < 2; ++u) {
        const int i  = u ? (127 - pp) : pp;   // 64-row q-tile
        const int Tt = i + 1;                 // 64-key subtiles
        const int Tq = (Tt + NPAR - 1) / NPAR;
        const int j0 = qq * Tq;
        const int j1 = (j0 + Tq < Tt) ? (j0 + Tq) : Tt;
        const int brow = qq*SEQ + i*64;

        if (j0 >= j1) {
            if (tid < 64) { g_mrow[brow + tid] = NEGINF; g_lrow[brow + tid] = 0.f; }
            continue;
        }

        __syncthreads();   // prior unit done reading Q/K/V smem
        // ones-block for l (V rows 128..143, first 128 bytes of each row)
        #pragma unroll
        for (int it = 0; it < 4; ++it) {
            int idx = tid + it*128;
            int r = idx >> 5, c = idx & 31;
            *(u32*)(sm + AV + (128 + r)*VSB + c*4) = 0x3C003C00u;
        }
        // load Q
        #pragma unroll
        for (int it = 0; it < 8; ++it) {
            int idx = tid + it*128;
            int r = idx >> 4, c = idx & 15;
            cpa16(sb + AQ + r*ASB + c*16, &g_Q[(size_t)(i*64 + r)*DH + c*8]);
        }
        CPCOMMIT();

        float o[16][4], ol[4];
        #pragma unroll
        for (int nt = 0; nt < 16; ++nt)
            #pragma unroll
            for (int c = 0; c < 4; ++c) o[nt][c] = 0.f;
        #pragma unroll
        for (int c = 0; c < 4; ++c) ol[c] = 0.f;
        float m0r = NEGINF, m1r = NEGINF;

        #pragma unroll 1
        for (int j = j0; j < j1; ++j) {
            if (j > j0) __syncthreads();   // all warps done reading K/V(j-1)
            issueKV(j);
            CPWAIT0();
            __syncthreads();               // Q/K/V visible

            // ---- S = Q K^T, single fp16 term ----
            float s[8][4];
            #pragma unroll
            for (int nt = 0; nt < 8; ++nt)
                #pragma unroll
                for (int c = 0; c < 4; ++c) s[nt][c] = 0.f;

            #pragma unroll
            for (int ks = 0; ks < 8; ++ks) {
                u32 qf[4];
                u32 qa = sb + AQ + (u32)((w*16 + aRow)*ASB + (ks*16 + aKB)*2);
                ldsm4(qa, qf[0], qf[1], qf[2], qf[3]);
                #pragma unroll
                for (int nbp = 0; nbp < 4; ++nbp) {
                    u32 kf[4];
                    u32 ba = sb + AK + (u32)((nbp*16 + bRow)*ASB + (ks*16 + bKB)*2);
                    ldsm4(ba, kf[0], kf[1], kf[2], kf[3]);
                    mma16816(s[nbp*2],   qf[0],qf[1],qf[2],qf[3], kf[0], kf[1]);
                    mma16816(s[nbp*2+1], qf[0],qf[1],qf[2],qf[3], kf[2], kf[3]);
                }
            }

            // ---- causal mask (diagonal subtile only) ----
            if (j == i) {
                const int gr0 = i*64 + rl0, gr1 = i*64 + rl1;
                #pragma unroll
                for (int nt = 0; nt < 8; ++nt) {
                    int gc = j*64 + nt*8 + (lane & 3)*2;
                    if (gc     > gr0) s[nt][0] = NEGINF;
                    if (gc + 1 > gr0) s[nt][1] = NEGINF;
                    if (gc     > gr1) s[nt][2] = NEGINF;
                    if (gc + 1 > gr1) s[nt][3] = NEGINF;
                }
            }

            // ---- online softmax (log2 domain, quad-local rows) ----
            float mx0 = NEGINF, mx1 = NEGINF;
            #pragma unroll
            for (int nt = 0; nt < 8; ++nt) {
                mx0 = fmaxf(mx0, fmaxf(s[nt][0], s[nt][1]));
                mx1 = fmaxf(mx1, fmaxf(s[nt][2], s[nt][3]));
            }
            mx0 = fmaxf(mx0, __shfl_xor_sync(0xffffffffu, mx0, 1));
            mx0 = fmaxf(mx0, __shfl_xor_sync(0xffffffffu, mx0, 2));
            mx1 = fmaxf(mx1, __shfl_xor_sync(0xffffffffu, mx1, 1));
            mx1 = fmaxf(mx1, __shfl_xor_sync(0xffffffffu, mx1, 2));

            float mn0 = fmaxf(m0r, mx0), mn1 = fmaxf(m1r, mx1);
            float al0 = ex2f(m0r - mn0), al1 = ex2f(m1r - mn1);
            m0r = mn0;  m1r = mn1;

            u32 p2[16];
            #pragma unroll
            for (int nt = 0; nt < 8; ++nt) {
                float p0  = ex2f(s[nt][0] - mn0);
                float p1  = ex2f(s[nt][1] - mn0);
                float p2f = ex2f(s[nt][2] - mn1);
                float p3  = ex2f(s[nt][3] - mn1);
                p2[nt*2]   = packh2(p0, p1);
                p2[nt*2+1] = packh2(p2f, p3);
            }

            bool need = (al0 < 1.f) || (al1 < 1.f);
            if (__ballot_sync(0xffffffffu, need)) {
                #pragma unroll
                for (int nt = 0; nt < 16; ++nt) {
                    o[nt][0] *= al0;  o[nt][1] *= al0;
                    o[nt][2] *= al1;  o[nt][3] *= al1;
                }
                ol[0] *= al0; ol[1] *= al0; ol[2] *= al1; ol[3] *= al1;
            }

            // ---- O += P * V ; l += P * ones (extra dim-block) ----
            #pragma unroll
            for (int t = 0; t < 4; ++t) {
                u32 lv[4];
                u32 la = sb + AV + (u32)((128 + bRow)*VSB + (t*16 + bKB)*2);
                ldsm4(la, lv[0], lv[1], lv[2], lv[3]);
                mma16816(ol, p2[4*t],p2[4*t+1],p2[4*t+2],p2[4*t+3], lv[0], lv[1]);
                #pragma unroll
                for (int nbp = 0; nbp < 8; ++nbp) {
                    u32 vh[4];
                    u32 ba = sb + AV + (u32)((nbp*16 + bRow)*VSB + (t*16 + bKB)*2);
                    ldsm4(ba, vh[0], vh[1], vh[2], vh[3]);
                    mma16816(o[nbp*2],   p2[4*t],p2[4*t+1],p2[4*t+2],p2[4*t+3], vh[0], vh[1]);
                    mma16816(o[nbp*2+1], p2[4*t],p2[4*t+1],p2[4*t+2],p2[4*t+3], vh[2], vh[3]);
                }
            }
        }

        // ---- store partials (l comes from the ones-column MMA) ----
        const int gr0 = brow + rl0, gr1 = brow + rl1;
        #pragma unroll
        for (int nt = 0; nt < 16; ++nt) {
            const int col = nt*8 + (lane & 3)*2;
            *(float2*)&g_Op[(size_t)gr0*DH + col] = make_float2(o[nt][0], o[nt][1]);
            *(float2*)&g_Op[(size_t)gr1*DH + col] = make_float2(o[nt][2], o[nt][3]);
        }
        if ((lane & 3) == 0) {
            g_mrow[gr0] = m0r;  g_lrow[gr0] = ol[0];
            g_mrow[gr1] = m1r;  g_lrow[gr1] = ol[2];
        }
    }
}

// =====================================================================
// Kernel 3: merge NPAR partials per row (LSE combine, log2 domain).
// =====================================================================
__global__ void merge_kernel(float* __restrict__ Out)
{
    const int t = threadIdx.x;
    const int row = blockIdx.x*4 + (t >> 5);
    const int c = (t & 31)*4;

    float mv[NPAR], lv[NPAR];
    float mmax = NEGINF;
    #pragma unroll
    for (int q = 0; q < NPAR; ++q) {
        mv[q] = g_mrow[q*SEQ + row];
        lv[q] = g_lrow[q*SEQ + row];
        if (lv[q] > 0.f) mmax = fmaxf(mmax, mv[q]);
    }
    float4 acc = make_float4(0.f, 0.f, 0.f, 0.f);
    float ws = 0.f;
    #pragma unroll
    for (int q = 0; q < NPAR; ++q) {
        if (lv[q] > 0.f) {
            float wgt = ex2f(mv[q] - mmax);
            float4 v = *(const float4*)&g_Op[((size_t)q*SEQ + row)*DH + c];
            acc.x += wgt*v.x; acc.y += wgt*v.y; acc.z += wgt*v.z; acc.w += wgt*v.w;
            ws += wgt * lv[q];
        }
    }
    float inv = 1.0f / ws;
    *(float4*)&Out[(size_t)row*DH + c] =
        make_float4(acc.x*inv, acc.y*inv, acc.z*inv, acc.w*inv);
}

// =====================================================================
extern "C" void kernel_launch(void* const* d_in, const int* in_sizes, int n_in,
                              void* d_out, int out_size)
{
    (void)in_sizes; (void)n_in; (void)out_size;
    const float* X  = (const float*)d_in[0];
    const float* Wq = (const float*)d_in[1];
    const float* Wk = (const float*)d_in[2];
    const float* Wv = (const float*)d_in[3];

    const int nTot = SEQ*DM/4 + 3*DH*DM/4;
    split_all_kernel<<<(nTot + 255)/256, 256>>>(
        (const float4*)X, (const float4*)Wq, (const float4*)Wk, (const float4*)Wv);

    const int PSM = 2*PSSZ;                 // 110592
    cudaFuncSetAttribute(proj_kernel, cudaFuncAttributeMaxDynamicSharedMemorySize, PSM);
    cudaFuncSetAttribute(attn_kernel, cudaFuncAttributeMaxDynamicSharedMemorySize, ASM_T);

    proj_kernel<<<dim3(128, 3), 256, PSM>>>();
    attn_kernel<<<NPAR*64, 128, ASM_T>>>();
    merge_kernel<<<SEQ/4, 128>>>((float*)d_out);
}

// round 13
// speedup vs baseline: 1.6285x; 1.2165x over previous
#include <cuda_runtime.h>
#include <cuda_fp16.h>
#include <cstdint>

typedef uint32_t u32;

#define SEQ 8192
#define DM  1024
#define DH  128
#define NPAR 6

#define NEGINF __int_as_float(0xff800000u)

// ---------------- device scratch (no allocs allowed) ----------------
__device__ __align__(16) __half g_Xh[SEQ*DM];
__device__ __align__(16) __half g_Wh[3*DH*DM], g_Wl[3*DH*DM];
__device__ __align__(16) __half g_Q[SEQ*DH];               // scaled by log2e/sqrt(dk)
__device__ __align__(16) __half g_K[SEQ*DH];
__device__ __align__(16) __half g_Vt[DH*SEQ];              // V transposed [dim][seq]
__device__ float g_Op[NPAR*SEQ*DH];
__device__ float g_mrow[NPAR*SEQ], g_lrow[NPAR*SEQ];

// ---------------- helpers ----------------
__device__ __forceinline__ u32 s2u(const void* p){
    u32 a; asm("{ .reg .u64 t; cvta.to.shared.u64 t, %1; cvt.u32.u64 %0, t; }" : "=r"(a) : "l"(p)); return a;
}
__device__ __forceinline__ void split2(float a, float b, u32 &h, u32 &l){
    __half2 hh = __floats2half2_rn(a, b);
    h = *reinterpret_cast<u32*>(&hh);
    float2 bk = __half22float2(hh);
    __half2 ll = __floats2half2_rn(a - bk.x, b - bk.y);
    l = *reinterpret_cast<u32*>(&ll);
}
__device__ __forceinline__ u32 packh2(float a, float b){
    __half2 hh = __floats2half2_rn(a, b);
    return *reinterpret_cast<u32*>(&hh);
}
__device__ __forceinline__ float ex2f(float x){
    float r; asm("ex2.approx.ftz.f32 %0, %1;" : "=f"(r) : "f"(x)); return r;
}
__device__ __forceinline__ void ldsm4(u32 a, u32 &r0, u32 &r1, u32 &r2, u32 &r3){
    asm volatile("ldmatrix.sync.aligned.m8n8.x4.shared.b16 {%0,%1,%2,%3}, [%4];"
        : "=r"(r0), "=r"(r1), "=r"(r2), "=r"(r3) : "r"(a));
}
__device__ __forceinline__ void mma16816(float* d, u32 a0, u32 a1, u32 a2, u32 a3, u32 b0, u32 b1){
    asm volatile("mma.sync.aligned.m16n8k16.row.col.f32.f16.f16.f32 "
        "{%0,%1,%2,%3},{%4,%5,%6,%7},{%8,%9},{%0,%1,%2,%3};"
        : "+f"(d[0]), "+f"(d[1]), "+f"(d[2]), "+f"(d[3])
        : "r"(a0), "r"(a1), "r"(a2), "r"(a3), "r"(b0), "r"(b1));
}
__device__ __forceinline__ void cpa16(u32 dst, const void* src){
    asm volatile("cp.async.cg.shared.global [%0], [%1], 16;" :: "r"(dst), "l"(src));
}
#define CPCOMMIT() asm volatile("cp.async.commit_group;" ::: "memory")
#define CPWAIT0()  asm volatile("cp.async.wait_group 0;" ::: "memory")

// =====================================================================
// Kernel 0: fp32 -> fp16 (X: hi only; W: split hi+lo)
// =====================================================================
__global__ void split_all_kernel(const float4* __restrict__ X,
                                 const float4* __restrict__ Wq,
                                 const float4* __restrict__ Wk,
                                 const float4* __restrict__ Wv)
{
    const int nX4 = SEQ*DM/4, nW4 = DH*DM/4;
    int i = blockIdx.x * blockDim.x + threadIdx.x;
    if (i < nX4) {
        float4 v = X[i];
        ((uint2*)g_Xh)[i] = make_uint2(packh2(v.x, v.y), packh2(v.z, v.w));
        return;
    }
    int k = i - nX4;
    if (k >= 3*nW4) return;
    int mat = k / nW4; int off = k - mat*nW4;
    const float4* src = (mat==0) ? Wq : (mat==1) ? Wk : Wv;
    uint2* dh = (uint2*)(g_Wh + (size_t)mat*DH*DM);
    uint2* dl = (uint2*)(g_Wl + (size_t)mat*DH*DM);
    float4 v = src[off];
    u32 h0, l0, h1, l1;
    split2(v.x, v.y, h0, l0);
    split2(v.z, v.w, h1, l1);
    dh[off] = make_uint2(h0, h1);
    dl[off] = make_uint2(l0, l1);
}

// =====================================================================
// Kernel 1: QKV projection, 2-term fp16 (Xh·Wh + Xh·Wl), 2-stream acc,
// cp.async 2-stage, 2 CTAs/SM. grid(128,3): M-tile 64. 256 thr.
// Q folded-scaled by log2e/sqrt(dk); Q/K single fp16; V transposed fp16.
// =====================================================================
#define PSB   144
#define PXH   0
#define PWH   9216
#define PWL   27648
#define PSSZ  46080

__global__ void __launch_bounds__(256,2) proj_kernel()
{
    extern __shared__ __align__(16) char sm[];
    const u32 sb = s2u(sm);

    const int tid = threadIdx.x, lane = tid & 31, wid = tid >> 5;
    const int wm = wid >> 2, wn = wid & 3;       // 2m x 4n
    const int m0 = blockIdx.x * 64, mat = blockIdx.y;
    const __half* __restrict__ Wbh = g_Wh + (size_t)mat*DH*DM;
    const __half* __restrict__ Wbl = g_Wl + (size_t)mat*DH*DM;
    // Q scale = log2(e)/sqrt(128); softmax runs in log2 domain
    const float scale = (mat==0) ? 0.1275174436f : 1.0f;

    const int aRow = lane & 15, aKB = (lane >> 4) << 3;
    const int bRow = (lane & 7) + ((lane >> 4) & 1) * 8, bKB = ((lane >> 3) & 1) << 3;

    auto issue = [&](int kc, int st){
        const u32 base = sb + st*PSSZ;
        #pragma unroll
        for (int it = 0; it < 2; ++it) {
            int idx = tid + it*256;
            int r = idx >> 3, c = idx & 7;
            cpa16(base + PXH + r*PSB + c*16, &g_Xh[(size_t)(m0 + r)*DM + kc*64 + c*8]);
        }
        #pragma unroll
        for (int it = 0; it < 4; ++it) {
            int idx = tid + it*256;
            int r = idx >> 3, c = idx & 7;
            cpa16(base + PWH + r*PSB + c*16, &Wbh[(size_t)r*DM + kc*64 + c*8]);
            cpa16(base + PWL + r*PSB + c*16, &Wbl[(size_t)r*DM + kc*64 + c*8]);
        }
        CPCOMMIT();
    };

    float a1[2][4][4], a2[2][4][4];
    #pragma unroll
    for (int i = 0; i < 2; ++i)
        #pragma unroll
        for (int j = 0; j < 4; ++j)
            #pragma unroll
            for (int c = 0; c < 4; ++c) { a1[i][j][c] = 0.f; a2[i][j][c] = 0.f; }

    issue(0, 0);
    for (int kc = 0; kc < 16; ++kc) {
        const int st = kc & 1;
        const u32 base = sb + st*PSSZ;
        CPWAIT0();
        __syncthreads();
        if (kc + 1 < 16) issue(kc + 1, st ^ 1);

        #pragma unroll
        for (int ks = 0; ks < 4; ++ks) {
            u32 ah[2][4];
            #pragma unroll
            for (int mt = 0; mt < 2; ++mt) {
                u32 qa = base + PXH + (u32)((wm*32 + mt*16 + aRow)*PSB + (ks*16 + aKB)*2);
                ldsm4(qa, ah[mt][0], ah[mt][1], ah[mt][2], ah[mt][3]);
            }
            #pragma unroll
            for (int nb = 0; nb < 2; ++nb) {
                u32 bh[4], bl[4];
                u32 ba = base + PWH + (u32)((wn*32 + nb*16 + bRow)*PSB + (ks*16 + bKB)*2);
                ldsm4(ba,             bh[0], bh[1], bh[2], bh[3]);
                ldsm4(ba + (PWL-PWH), bl[0], bl[1], bl[2], bl[3]);
                #pragma unroll
                for (int mt = 0; mt < 2; ++mt) {
                    mma16816(a1[mt][nb*2],   ah[mt][0],ah[mt][1],ah[mt][2],ah[mt][3], bh[0], bh[1]);
                    mma16816(a2[mt][nb*2],   ah[mt][0],ah[mt][1],ah[mt][2],ah[mt][3], bl[0], bl[1]);
                    mma16816(a1[mt][nb*2+1], ah[mt][0],ah[mt][1],ah[mt][2],ah[mt][3], bh[2], bh[3]);
                    mma16816(a2[mt][nb*2+1], ah[mt][0],ah[mt][1],ah[mt][2],ah[mt][3], bl[2], bl[3]);
                }
            }
        }
        __syncthreads();
    }

    #pragma unroll
    for (int mt = 0; mt < 2; ++mt) {
        const int r0 = m0 + wm*32 + mt*16 + (lane >> 2);
        const int r1 = r0 + 8;
        #pragma unroll
        for (int nt = 0; nt < 4; ++nt) {
            const int col = wn*32 + nt*8 + (lane & 3)*2;
            float c0 = (a1[mt][nt][0] + a2[mt][nt][0])*scale;
            float c1 = (a1[mt][nt][1] + a2[mt][nt][1])*scale;
            float c2 = (a1[mt][nt][2] + a2[mt][nt][2])*scale;
            float c3 = (a1[mt][nt][3] + a2[mt][nt][3])*scale;
            if (mat < 2) {
                __half* G = (mat==0) ? g_Q : g_K;
                *(u32*)&G[(size_t)r0*DH + col] = packh2(c0, c1);
                *(u32*)&G[(size_t)r1*DH + col] = packh2(c2, c3);
            } else {
                g_Vt[(size_t)(col    )*SEQ + r0] = __float2half_rn(c0);
                g_Vt[(size_t)(col + 1)*SEQ + r0] = __float2half_rn(c1);
                g_Vt[(size_t)(col    )*SEQ + r1] = __float2half_rn(c2);
                g_Vt[(size_t)(col + 1)*SEQ + r1] = __float2half_rn(c3);
            }
        }
    }
}

// =====================================================================
// Kernel 2: causal flash attention, all-fp16 operands (error-budgeted),
// log2-domain softmax, l computed by the PV MMA via a ones-block in V.
// 384 CTAs x 128 thr, 55.5KB smem -> 3 CTAs/SM (3-way cross-CTA overlap).
// CTA (qq,pp): KV-sixth qq of 64-row q-tiles pp & 127-pp.
// =====================================================================
#define ASB   272            // Q/K row stride bytes (128 kcols fp16 + pad)
#define VSB   144            // V row stride bytes (64 key cols fp16 + pad)
#define AQ    0              // Q: 64 x 272 = 17408
#define AK    17408          // K: 64 x 272 = 17408
#define AV    34816          // V: 144 x 144 = 20736 (rows 128..143 = ones)
#define ASM_T 55552

__global__ void __launch_bounds__(128,3) attn_kernel()
{
    extern __shared__ __align__(16) char sm[];
    const u32 sb = s2u(sm);

    const int tid = threadIdx.x, lane = tid & 31, w = tid >> 5;
    const int qq = blockIdx.x >> 6;   // kv sixth 0..5
    const int pp = blockIdx.x & 63;   // pair id 0..63

    const int aRow = lane & 15, aKB = (lane >> 4) << 3;
    const int bRow = (lane & 7) + ((lane >> 4) & 1) * 8, bKB = ((lane >> 3) & 1) << 3;
    const int rl0 = w*16 + (lane >> 2);   // local q-row (0..63)
    const int rl1 = rl0 + 8;

    auto issueKV = [&](int j){
        #pragma unroll
        for (int it = 0; it < 8; ++it) {     // K: 64 rows x 16 chunks
            int idx = tid + it*128;
            int r = idx >> 4, c = idx & 15;
            cpa16(sb + AK + r*ASB + c*16, &g_K[(size_t)(j*64 + r)*DH + c*8]);
        }
        #pragma unroll
        for (int it = 0; it < 8; ++it) {     // V: 128 dim-rows x 8 chunks
            int idx = tid + it*128;
            int r = idx >> 3, c = idx & 7;
            cpa16(sb + AV + r*VSB + c*16, &g_Vt[(size_t)r*SEQ + j*64 + c*8]);
        }
        CPCOMMIT();
    };

    #pragma unroll 1
    for (int u = 0; u < 2; ++u) {
        const int i  = u ? (127 - pp) : pp;   // 64-row q-tile
        const int Tt = i + 1;                 // 64-key subtiles
        const int Tq = (Tt + NPAR - 1) / NPAR;
        const int j0 = qq * Tq;
        const int j1 = (j0 + Tq < Tt) ? (j0 + Tq) : Tt;
        const int brow = qq*SEQ + i*64;

        if (j0 >= j1) {
            if (tid < 64) { g_mrow[brow + tid] = NEGINF; g_lrow[brow + tid] = 0.f; }
            continue;
        }

        __syncthreads();   // prior unit done reading Q/K/V smem
        // ones-block for l (V rows 128..143, first 128 bytes of each row)
        #pragma unroll
        for (int it = 0; it < 4; ++it) {
            int idx = tid + it*128;
            int r = idx >> 5, c = idx & 31;
            *(u32*)(sm + AV + (128 + r)*VSB + c*4) = 0x3C003C00u;
        }
        // load Q
        #pragma unroll
        for (int it = 0; it < 8; ++it) {
            int idx = tid + it*128;
            int r = idx >> 4, c = idx & 15;
            cpa16(sb + AQ + r*ASB + c*16, &g_Q[(size_t)(i*64 + r)*DH + c*8]);
        }
        CPCOMMIT();

        float o[16][4], ol[4];
        #pragma unroll
        for (int nt = 0; nt < 16; ++nt)
            #pragma unroll
            for (int c = 0; c < 4; ++c) o[nt][c] = 0.f;
        #pragma unroll
        for (int c = 0; c < 4; ++c) ol[c] = 0.f;
        float m0r = NEGINF, m1r = NEGINF;

        #pragma unroll 1
        for (int j = j0; j < j1; ++j) {
            if (j > j0) __syncthreads();   // all warps done reading K/V(j-1)
            issueKV(j);
            CPWAIT0();
            __syncthreads();               // Q/K/V visible

            // ---- S = Q K^T, single fp16 term ----
            float s[8][4];
            #pragma unroll
            for (int nt = 0; nt < 8; ++nt)
                #pragma unroll
                for (int c = 0; c < 4; ++c) s[nt][c] = 0.f;

            #pragma unroll
            for (int ks = 0; ks < 8; ++ks) {
                u32 qf[4];
                u32 qa = sb + AQ + (u32)((w*16 + aRow)*ASB + (ks*16 + aKB)*2);
                ldsm4(qa, qf[0], qf[1], qf[2], qf[3]);
                #pragma unroll
                for (int nbp = 0; nbp < 4; ++nbp) {
                    u32 kf[4];
                    u32 ba = sb + AK + (u32)((nbp*16 + bRow)*ASB + (ks*16 + bKB)*2);
                    ldsm4(ba, kf[0], kf[1], kf[2], kf[3]);
                    mma16816(s[nbp*2],   qf[0],qf[1],qf[2],qf[3], kf[0], kf[1]);
                    mma16816(s[nbp*2+1], qf[0],qf[1],qf[2],qf[3], kf[2], kf[3]);
                }
            }

            // ---- causal mask (diagonal subtile only) ----
            if (j == i) {
                const int gr0 = i*64 + rl0, gr1 = i*64 + rl1;
                #pragma unroll
                for (int nt = 0; nt < 8; ++nt) {
                    int gc = j*64 + nt*8 + (lane & 3)*2;
                    if (gc     > gr0) s[nt][0] = NEGINF;
                    if (gc + 1 > gr0) s[nt][1] = NEGINF;
                    if (gc     > gr1) s[nt][2] = NEGINF;
                    if (gc + 1 > gr1) s[nt][3] = NEGINF;
                }
            }

            // ---- online softmax (log2 domain, quad-local rows) ----
            float mx0 = NEGINF, mx1 = NEGINF;
            #pragma unroll
            for (int nt = 0; nt < 8; ++nt) {
                mx0 = fmaxf(mx0, fmaxf(s[nt][0], s[nt][1]));
                mx1 = fmaxf(mx1, fmaxf(s[nt][2], s[nt][3]));
            }
            mx0 = fmaxf(mx0, __shfl_xor_sync(0xffffffffu, mx0, 1));
            mx0 = fmaxf(mx0, __shfl_xor_sync(0xffffffffu, mx0, 2));
            mx1 = fmaxf(mx1, __shfl_xor_sync(0xffffffffu, mx1, 1));
            mx1 = fmaxf(mx1, __shfl_xor_sync(0xffffffffu, mx1, 2));

            float mn0 = fmaxf(m0r, mx0), mn1 = fmaxf(m1r, mx1);
            float al0 = ex2f(m0r - mn0), al1 = ex2f(m1r - mn1);
            m0r = mn0;  m1r = mn1;

            u32 p2[16];
            #pragma unroll
            for (int nt = 0; nt < 8; ++nt) {
                float p0  = ex2f(s[nt][0] - mn0);
                float p1  = ex2f(s[nt][1] - mn0);
                float p2f = ex2f(s[nt][2] - mn1);
                float p3  = ex2f(s[nt][3] - mn1);
                p2[nt*2]   = packh2(p0, p1);
                p2[nt*2+1] = packh2(p2f, p3);
            }

            bool need = (al0 < 1.f) || (al1 < 1.f);
            if (__ballot_sync(0xffffffffu, need)) {
                #pragma unroll
                for (int nt = 0; nt < 16; ++nt) {
                    o[nt][0] *= al0;  o[nt][1] *= al0;
                    o[nt][2] *= al1;  o[nt][3] *= al1;
                }
                ol[0] *= al0; ol[1] *= al0; ol[2] *= al1; ol[3] *= al1;
            }

            // ---- O += P * V ; l += P * ones (extra dim-block) ----
            #pragma unroll
            for (int t = 0; t < 4; ++t) {
                u32 lv[4];
                u32 la = sb + AV + (u32)((128 + bRow)*VSB + (t*16 + bKB)*2);
                ldsm4(la, lv[0], lv[1], lv[2], lv[3]);
                mma16816(ol, p2[4*t],p2[4*t+1],p2[4*t+2],p2[4*t+3], lv[0], lv[1]);
                #pragma unroll
                for (int nbp = 0; nbp < 8; ++nbp) {
                    u32 vh[4];
                    u32 ba = sb + AV + (u32)((nbp*16 + bRow)*VSB + (t*16 + bKB)*2);
                    ldsm4(ba, vh[0], vh[1], vh[2], vh[3]);
                    mma16816(o[nbp*2],   p2[4*t],p2[4*t+1],p2[4*t+2],p2[4*t+3], vh[0], vh[1]);
                    mma16816(o[nbp*2+1], p2[4*t],p2[4*t+1],p2[4*t+2],p2[4*t+3], vh[2], vh[3]);
                }
            }
        }

        // ---- store partials (l comes from the ones-column MMA) ----
        const int gr0 = brow + rl0, gr1 = brow + rl1;
        #pragma unroll
        for (int nt = 0; nt < 16; ++nt) {
            const int col = nt*8 + (lane & 3)*2;
            *(float2*)&g_Op[(size_t)gr0*DH + col] = make_float2(o[nt][0], o[nt][1]);
            *(float2*)&g_Op[(size_t)gr1*DH + col] = make_float2(o[nt][2], o[nt][3]);
        }
        if ((lane & 3) == 0) {
            g_mrow[gr0] = m0r;  g_lrow[gr0] = ol[0];
            g_mrow[gr1] = m1r;  g_lrow[gr1] = ol[2];
        }
    }
}

// =====================================================================
// Kernel 3: merge NPAR partials per row (LSE combine, log2 domain).
// =====================================================================
__global__ void merge_kernel(float* __restrict__ Out)
{
    const int t = threadIdx.x;
    const int row = blockIdx.x*4 + (t >> 5);
    const int c = (t & 31)*4;

    float mv[NPAR], lv[NPAR];
    float mmax = NEGINF;
    #pragma unroll
    for (int q = 0; q < NPAR; ++q) {
        mv[q] = g_mrow[q*SEQ + row];
        lv[q] = g_lrow[q*SEQ + row];
        if (lv[q] > 0.f) mmax = fmaxf(mmax, mv[q]);
    }
    float4 acc = make_float4(0.f, 0.f, 0.f, 0.f);
    float ws = 0.f;
    #pragma unroll
    for (int q = 0; q < NPAR; ++q) {
        if (lv[q] > 0.f) {
            float wgt = ex2f(mv[q] - mmax);
            float4 v = *(const float4*)&g_Op[((size_t)q*SEQ + row)*DH + c];
            acc.x += wgt*v.x; acc.y += wgt*v.y; acc.z += wgt*v.z; acc.w += wgt*v.w;
            ws += wgt * lv[q];
        }
    }
    float inv = 1.0f / ws;
    *(float4*)&Out[(size_t)row*DH + c] =
        make_float4(acc.x*inv, acc.y*inv, acc.z*inv, acc.w*inv);
}

// =====================================================================
extern "C" void kernel_launch(void* const* d_in, const int* in_sizes, int n_in,
                              void* d_out, int out_size)
{
    (void)in_sizes; (void)n_in; (void)out_size;
    const float* X  = (const float*)d_in[0];
    const float* Wq = (const float*)d_in[1];
    const float* Wk = (const float*)d_in[2];
    const float* Wv = (const float*)d_in[3];

    const int nTot = SEQ*DM/4 + 3*DH*DM/4;
    split_all_kernel<<<(nTot + 255)/256, 256>>>(
        (const float4*)X, (const float4*)Wq, (const float4*)Wk, (const float4*)Wv);

    const int PSM = 2*PSSZ;                 // 92160 (2 CTAs/SM)
    cudaFuncSetAttribute(proj_kernel, cudaFuncAttributeMaxDynamicSharedMemorySize, PSM);
    cudaFuncSetAttribute(attn_kernel, cudaFuncAttributeMaxDynamicSharedMemorySize, ASM_T);

    proj_kernel<<<dim3(128, 3), 256, PSM>>>();
    attn_kernel<<<NPAR*64, 128, ASM_T>>>();
    merge_kernel<<<SEQ/4, 128>>>((float*)d_out);
}

// round 14
// speedup vs baseline: 1.6478x; 1.0119x over previous
#include <cuda_runtime.h>
#include <cuda_fp16.h>
#include <cstdint>

typedef uint32_t u32;

#define SEQ 8192
#define DM  1024
#define DH  128
#define NPAR 6
#define NUNITS (128*NPAR)

#define NEGINF __int_as_float(0xff800000u)

// ---------------- device scratch (no allocs allowed) ----------------
__device__ __align__(16) __half g_Xh[SEQ*DM];
__device__ __align__(16) __half g_Wh[3*DH*DM], g_Wl[3*DH*DM];
__device__ __align__(16) __half g_Q[SEQ*DH];               // scaled by log2e/sqrt(dk)
__device__ __align__(16) __half g_K[SEQ*DH];
__device__ __align__(16) __half g_Vt[DH*SEQ];              // V transposed [dim][seq]
__device__ float g_Op[NPAR*SEQ*DH];
__device__ float g_mrow[NPAR*SEQ], g_lrow[NPAR*SEQ];
__device__ u32 g_ctr;                                      // persistent work counter

// ---------------- helpers ----------------
__device__ __forceinline__ u32 s2u(const void* p){
    u32 a; asm("{ .reg .u64 t; cvta.to.shared.u64 t, %1; cvt.u32.u64 %0, t; }" : "=r"(a) : "l"(p)); return a;
}
__device__ __forceinline__ void split2(float a, float b, u32 &h, u32 &l){
    __half2 hh = __floats2half2_rn(a, b);
    h = *reinterpret_cast<u32*>(&hh);
    float2 bk = __half22float2(hh);
    __half2 ll = __floats2half2_rn(a - bk.x, b - bk.y);
    l = *reinterpret_cast<u32*>(&ll);
}
__device__ __forceinline__ u32 packh2(float a, float b){
    __half2 hh = __floats2half2_rn(a, b);
    return *reinterpret_cast<u32*>(&hh);
}
__device__ __forceinline__ float ex2f(float x){
    float r; asm("ex2.approx.ftz.f32 %0, %1;" : "=f"(r) : "f"(x)); return r;
}
__device__ __forceinline__ void ldsm4(u32 a, u32 &r0, u32 &r1, u32 &r2, u32 &r3){
    asm volatile("ldmatrix.sync.aligned.m8n8.x4.shared.b16 {%0,%1,%2,%3}, [%4];"
        : "=r"(r0), "=r"(r1), "=r"(r2), "=r"(r3) : "r"(a));
}
__device__ __forceinline__ void mma16816(float* d, u32 a0, u32 a1, u32 a2, u32 a3, u32 b0, u32 b1){
    asm volatile("mma.sync.aligned.m16n8k16.row.col.f32.f16.f16.f32 "
        "{%0,%1,%2,%3},{%4,%5,%6,%7},{%8,%9},{%0,%1,%2,%3};"
        : "+f"(d[0]), "+f"(d[1]), "+f"(d[2]), "+f"(d[3])
        : "r"(a0), "r"(a1), "r"(a2), "r"(a3), "r"(b0), "r"(b1));
}
__device__ __forceinline__ void cpa16(u32 dst, const void* src){
    asm volatile("cp.async.cg.shared.global [%0], [%1], 16;" :: "r"(dst), "l"(src));
}
#define CPCOMMIT() asm volatile("cp.async.commit_group;" ::: "memory")
#define CPWAIT0()  asm volatile("cp.async.wait_group 0;" ::: "memory")

// =====================================================================
// Kernel 0: fp32 -> fp16 (X: hi only; W: split hi+lo) + counter reset
// =====================================================================
__global__ void split_all_kernel(const float4* __restrict__ X,
                                 const float4* __restrict__ Wq,
                                 const float4* __restrict__ Wk,
                                 const float4* __restrict__ Wv)
{
    if (blockIdx.x == 0 && threadIdx.x == 0) g_ctr = 0u;   // reset work queue
    const int nX4 = SEQ*DM/4, nW4 = DH*DM/4;
    int i = blockIdx.x * blockDim.x + threadIdx.x;
    if (i < nX4) {
        float4 v = X[i];
        ((uint2*)g_Xh)[i] = make_uint2(packh2(v.x, v.y), packh2(v.z, v.w));
        return;
    }
    int k = i - nX4;
    if (k >= 3*nW4) return;
    int mat = k / nW4; int off = k - mat*nW4;
    const float4* src = (mat==0) ? Wq : (mat==1) ? Wk : Wv;
    uint2* dh = (uint2*)(g_Wh + (size_t)mat*DH*DM);
    uint2* dl = (uint2*)(g_Wl + (size_t)mat*DH*DM);
    float4 v = src[off];
    u32 h0, l0, h1, l1;
    split2(v.x, v.y, h0, l0);
    split2(v.z, v.w, h1, l1);
    dh[off] = make_uint2(h0, h1);
    dl[off] = make_uint2(l0, l1);
}

// =====================================================================
// Kernel 1: QKV projection, 2-term fp16 (Xh·Wh + Xh·Wl), 2-stream acc,
// cp.async 2-stage, 2 CTAs/SM. grid(128,3): M-tile 64. 256 thr.
// =====================================================================
#define PSB   144
#define PXH   0
#define PWH   9216
#define PWL   27648
#define PSSZ  46080

__global__ void __launch_bounds__(256,2) proj_kernel()
{
    extern __shared__ __align__(16) char sm[];
    const u32 sb = s2u(sm);

    const int tid = threadIdx.x, lane = tid & 31, wid = tid >> 5;
    const int wm = wid >> 2, wn = wid & 3;       // 2m x 4n
    const int m0 = blockIdx.x * 64, mat = blockIdx.y;
    const __half* __restrict__ Wbh = g_Wh + (size_t)mat*DH*DM;
    const __half* __restrict__ Wbl = g_Wl + (size_t)mat*DH*DM;
    const float scale = (mat==0) ? 0.1275174436f : 1.0f;   // log2e/sqrt(128)

    const int aRow = lane & 15, aKB = (lane >> 4) << 3;
    const int bRow = (lane & 7) + ((lane >> 4) & 1) * 8, bKB = ((lane >> 3) & 1) << 3;

    auto issue = [&](int kc, int st){
        const u32 base = sb + st*PSSZ;
        #pragma unroll
        for (int it = 0; it < 2; ++it) {
            int idx = tid + it*256;
            int r = idx >> 3, c = idx & 7;
            cpa16(base + PXH + r*PSB + c*16, &g_Xh[(size_t)(m0 + r)*DM + kc*64 + c*8]);
        }
        #pragma unroll
        for (int it = 0; it < 4; ++it) {
            int idx = tid + it*256;
            int r = idx >> 3, c = idx & 7;
            cpa16(base + PWH + r*PSB + c*16, &Wbh[(size_t)r*DM + kc*64 + c*8]);
            cpa16(base + PWL + r*PSB + c*16, &Wbl[(size_t)r*DM + kc*64 + c*8]);
        }
        CPCOMMIT();
    };

    float a1[2][4][4], a2[2][4][4];
    #pragma unroll
    for (int i = 0; i < 2; ++i)
        #pragma unroll
        for (int j = 0; j < 4; ++j)
            #pragma unroll
            for (int c = 0; c < 4; ++c) { a1[i][j][c] = 0.f; a2[i][j][c] = 0.f; }

    issue(0, 0);
    for (int kc = 0; kc < 16; ++kc) {
        const int st = kc & 1;
        const u32 base = sb + st*PSSZ;
        CPWAIT0();
        __syncthreads();
        if (kc + 1 < 16) issue(kc + 1, st ^ 1);

        #pragma unroll
        for (int ks = 0; ks < 4; ++ks) {
            u32 ah[2][4];
            #pragma unroll
            for (int mt = 0; mt < 2; ++mt) {
                u32 qa = base + PXH + (u32)((wm*32 + mt*16 + aRow)*PSB + (ks*16 + aKB)*2);
                ldsm4(qa, ah[mt][0], ah[mt][1], ah[mt][2], ah[mt][3]);
            }
            #pragma unroll
            for (int nb = 0; nb < 2; ++nb) {
                u32 bh[4], bl[4];
                u32 ba = base + PWH + (u32)((wn*32 + nb*16 + bRow)*PSB + (ks*16 + bKB)*2);
                ldsm4(ba,             bh[0], bh[1], bh[2], bh[3]);
                ldsm4(ba + (PWL-PWH), bl[0], bl[1], bl[2], bl[3]);
                #pragma unroll
                for (int mt = 0; mt < 2; ++mt) {
                    mma16816(a1[mt][nb*2],   ah[mt][0],ah[mt][1],ah[mt][2],ah[mt][3], bh[0], bh[1]);
                    mma16816(a2[mt][nb*2],   ah[mt][0],ah[mt][1],ah[mt][2],ah[mt][3], bl[0], bl[1]);
                    mma16816(a1[mt][nb*2+1], ah[mt][0],ah[mt][1],ah[mt][2],ah[mt][3], bh[2], bh[3]);
                    mma16816(a2[mt][nb*2+1], ah[mt][0],ah[mt][1],ah[mt][2],ah[mt][3], bl[2], bl[3]);
                }
            }
        }
        __syncthreads();
    }

    #pragma unroll
    for (int mt = 0; mt < 2; ++mt) {
        const int r0 = m0 + wm*32 + mt*16 + (lane >> 2);
        const int r1 = r0 + 8;
        #pragma unroll
        for (int nt = 0; nt < 4; ++nt) {
            const int col = wn*32 + nt*8 + (lane & 3)*2;
            float c0 = (a1[mt][nt][0] + a2[mt][nt][0])*scale;
            float c1 = (a1[mt][nt][1] + a2[mt][nt][1])*scale;
            float c2 = (a1[mt][nt][2] + a2[mt][nt][2])*scale;
            float c3 = (a1[mt][nt][3] + a2[mt][nt][3])*scale;
            if (mat < 2) {
                __half* G = (mat==0) ? g_Q : g_K;
                *(u32*)&G[(size_t)r0*DH + col] = packh2(c0, c1);
                *(u32*)&G[(size_t)r1*DH + col] = packh2(c2, c3);
            } else {
                g_Vt[(size_t)(col    )*SEQ + r0] = __float2half_rn(c0);
                g_Vt[(size_t)(col + 1)*SEQ + r0] = __float2half_rn(c1);
                g_Vt[(size_t)(col    )*SEQ + r1] = __float2half_rn(c2);
                g_Vt[(size_t)(col + 1)*SEQ + r1] = __float2half_rn(c3);
            }
        }
    }
}

// =====================================================================
// Kernel 2: causal flash attention, all-fp16, log2-domain softmax,
// l via ones-block PV-MMA. PERSISTENT: 444 CTAs (=148 SMs x 3), work
// units (q-tile i, KV-sixth q) pulled big-first from a global counter
// (LPT greedy -> near-perfect per-SM balance + uniform 3-way overlap).
// =====================================================================
#define ASB   272            // Q/K row stride bytes
#define VSB   144            // V row stride bytes
#define AQ    0              // Q: 64 x 272 = 17408
#define AK    17408          // K: 64 x 272 = 17408
#define AV    34816          // V: 144 x 144 = 20736 (rows 128..143 = ones)
#define ASM_T 55552

__global__ void __launch_bounds__(128,3) attn_kernel()
{
    extern __shared__ __align__(16) char sm[];
    __shared__ u32 s_unit;
    const u32 sb = s2u(sm);

    const int tid = threadIdx.x, lane = tid & 31, w = tid >> 5;

    const int aRow = lane & 15, aKB = (lane >> 4) << 3;
    const int bRow = (lane & 7) + ((lane >> 4) & 1) * 8, bKB = ((lane >> 3) & 1) << 3;
    const int rl0 = w*16 + (lane >> 2);   // local q-row (0..63)
    const int rl1 = rl0 + 8;

    auto issueKV = [&](int j){
        #pragma unroll
        for (int it = 0; it < 8; ++it) {     // K: 64 rows x 16 chunks
            int idx = tid + it*128;
            int r = idx >> 4, c = idx & 15;
            cpa16(sb + AK + r*ASB + c*16, &g_K[(size_t)(j*64 + r)*DH + c*8]);
        }
        #pragma unroll
        for (int it = 0; it < 8; ++it) {     // V: 128 dim-rows x 8 chunks
            int idx = tid + it*128;
            int r = idx >> 3, c = idx & 7;
            cpa16(sb + AV + r*VSB + c*16, &g_Vt[(size_t)r*SEQ + j*64 + c*8]);
        }
        CPCOMMIT();
    };

    #pragma unroll 1
    while (true) {
        __syncthreads();   // prior unit done with smem + s_unit
        if (tid == 0) s_unit = atomicAdd(&g_ctr, 1u);
        __syncthreads();
        const u32 u = s_unit;
        if (u >= (u32)NUNITS) break;

        const int i  = 127 - (int)(u / NPAR);   // big tiles first (LPT)
        const int qq = (int)(u % NPAR);
        const int Tt = i + 1;                   // 64-key subtiles
        const int Tq = (Tt + NPAR - 1) / NPAR;
        const int j0 = qq * Tq;
        const int j1 = (j0 + Tq < Tt) ? (j0 + Tq) : Tt;
        const int brow = qq*SEQ + i*64;

        if (j0 >= j1) {
            if (tid < 64) { g_mrow[brow + tid] = NEGINF; g_lrow[brow + tid] = 0.f; }
            continue;
        }

        // ones-block for l (V rows 128..143, first 128 bytes of each row)
        #pragma unroll
        for (int it = 0; it < 4; ++it) {
            int idx = tid + it*128;
            int r = idx >> 5, c = idx & 31;
            *(u32*)(sm + AV + (128 + r)*VSB + c*4) = 0x3C003C00u;
        }
        // load Q
        #pragma unroll
        for (int it = 0; it < 8; ++it) {
            int idx = tid + it*128;
            int r = idx >> 4, c = idx & 15;
            cpa16(sb + AQ + r*ASB + c*16, &g_Q[(size_t)(i*64 + r)*DH + c*8]);
        }
        CPCOMMIT();

        float o[16][4], ol[4];
        #pragma unroll
        for (int nt = 0; nt < 16; ++nt)
            #pragma unroll
            for (int c = 0; c < 4; ++c) o[nt][c] = 0.f;
        #pragma unroll
        for (int c = 0; c < 4; ++c) ol[c] = 0.f;
        float m0r = NEGINF, m1r = NEGINF;

        #pragma unroll 1
        for (int j = j0; j < j1; ++j) {
            if (j > j0) __syncthreads();   // all warps done reading K/V(j-1)
            issueKV(j);
            CPWAIT0();
            __syncthreads();               // Q/K/V visible

            // ---- S = Q K^T, single fp16 term ----
            float s[8][4];
            #pragma unroll
            for (int nt = 0; nt < 8; ++nt)
                #pragma unroll
                for (int c = 0; c < 4; ++c) s[nt][c] = 0.f;

            #pragma unroll
            for (int ks = 0; ks < 8; ++ks) {
                u32 qf[4];
                u32 qa = sb + AQ + (u32)((w*16 + aRow)*ASB + (ks*16 + aKB)*2);
                ldsm4(qa, qf[0], qf[1], qf[2], qf[3]);
                #pragma unroll
                for (int nbp = 0; nbp < 4; ++nbp) {
                    u32 kf[4];
                    u32 ba = sb + AK + (u32)((nbp*16 + bRow)*ASB + (ks*16 + bKB)*2);
                    ldsm4(ba, kf[0], kf[1], kf[2], kf[3]);
                    mma16816(s[nbp*2],   qf[0],qf[1],qf[2],qf[3], kf[0], kf[1]);
                    mma16816(s[nbp*2+1], qf[0],qf[1],qf[2],qf[3], kf[2], kf[3]);
                }
            }

            // ---- causal mask (diagonal subtile only) ----
            if (j == i) {
                const int gr0 = i*64 + rl0, gr1 = i*64 + rl1;
                #pragma unroll
                for (int nt = 0; nt < 8; ++nt) {
                    int gc = j*64 + nt*8 + (lane & 3)*2;
                    if (gc     > gr0) s[nt][0] = NEGINF;
                    if (gc + 1 > gr0) s[nt][1] = NEGINF;
                    if (gc     > gr1) s[nt][2] = NEGINF;
                    if (gc + 1 > gr1) s[nt][3] = NEGINF;
                }
            }

            // ---- online softmax (log2 domain, quad-local rows) ----
            float mx0 = NEGINF, mx1 = NEGINF;
            #pragma unroll
            for (int nt = 0; nt < 8; ++nt) {
                mx0 = fmaxf(mx0, fmaxf(s[nt][0], s[nt][1]));
                mx1 = fmaxf(mx1, fmaxf(s[nt][2], s[nt][3]));
            }
            mx0 = fmaxf(mx0, __shfl_xor_sync(0xffffffffu, mx0, 1));
            mx0 = fmaxf(mx0, __shfl_xor_sync(0xffffffffu, mx0, 2));
            mx1 = fmaxf(mx1, __shfl_xor_sync(0xffffffffu, mx1, 1));
            mx1 = fmaxf(mx1, __shfl_xor_sync(0xffffffffu, mx1, 2));

            float mn0 = fmaxf(m0r, mx0), mn1 = fmaxf(m1r, mx1);
            float al0 = ex2f(m0r - mn0), al1 = ex2f(m1r - mn1);
            m0r = mn0;  m1r = mn1;

            u32 p2[16];
            #pragma unroll
            for (int nt = 0; nt < 8; ++nt) {
                float p0  = ex2f(s[nt][0] - mn0);
                float p1  = ex2f(s[nt][1] - mn0);
                float p2f = ex2f(s[nt][2] - mn1);
                float p3  = ex2f(s[nt][3] - mn1);
                p2[nt*2]   = packh2(p0, p1);
                p2[nt*2+1] = packh2(p2f, p3);
            }

            bool need = (al0 < 1.f) || (al1 < 1.f);
            if (__ballot_sync(0xffffffffu, need)) {
                #pragma unroll
                for (int nt = 0; nt < 16; ++nt) {
                    o[nt][0] *= al0;  o[nt][1] *= al0;
                    o[nt][2] *= al1;  o[nt][3] *= al1;
                }
                ol[0] *= al0; ol[1] *= al0; ol[2] *= al1; ol[3] *= al1;
            }

            // ---- O += P * V ; l += P * ones (extra dim-block) ----
            #pragma unroll
            for (int t = 0; t < 4; ++t) {
                u32 lv[4];
                u32 la = sb + AV + (u32)((128 + bRow)*VSB + (t*16 + bKB)*2);
                ldsm4(la, lv[0], lv[1], lv[2], lv[3]);
                mma16816(ol, p2[4*t],p2[4*t+1],p2[4*t+2],p2[4*t+3], lv[0], lv[1]);
                #pragma unroll
                for (int nbp = 0; nbp < 8; ++nbp) {
                    u32 vh[4];
                    u32 ba = sb + AV + (u32)((nbp*16 + bRow)*VSB + (t*16 + bKB)*2);
                    ldsm4(ba, vh[0], vh[1], vh[2], vh[3]);
                    mma16816(o[nbp*2],   p2[4*t],p2[4*t+1],p2[4*t+2],p2[4*t+3], vh[0], vh[1]);
                    mma16816(o[nbp*2+1], p2[4*t],p2[4*t+1],p2[4*t+2],p2[4*t+3], vh[2], vh[3]);
                }
            }
        }

        // ---- store partials (l from the ones-column MMA) ----
        const int gr0 = brow + rl0, gr1 = brow + rl1;
        #pragma unroll
        for (int nt = 0; nt < 16; ++nt) {
            const int col = nt*8 + (lane & 3)*2;
            *(float2*)&g_Op[(size_t)gr0*DH + col] = make_float2(o[nt][0], o[nt][1]);
            *(float2*)&g_Op[(size_t)gr1*DH + col] = make_float2(o[nt][2], o[nt][3]);
        }
        if ((lane & 3) == 0) {
            g_mrow[gr0] = m0r;  g_lrow[gr0] = ol[0];
            g_mrow[gr1] = m1r;  g_lrow[gr1] = ol[2];
        }
    }
}

// =====================================================================
// Kernel 3: merge NPAR partials per row (LSE combine, log2 domain).
// =====================================================================
__global__ void merge_kernel(float* __restrict__ Out)
{
    const int t = threadIdx.x;
    const int row = blockIdx.x*4 + (t >> 5);
    const int c = (t & 31)*4;

    float mv[NPAR], lv[NPAR];
    float mmax = NEGINF;
    #pragma unroll
    for (int q = 0; q < NPAR; ++q) {
        mv[q] = g_mrow[q*SEQ + row];
        lv[q] = g_lrow[q*SEQ + row];
        if (lv[q] > 0.f) mmax = fmaxf(mmax, mv[q]);
    }
    float4 acc = make_float4(0.f, 0.f, 0.f, 0.f);
    float ws = 0.f;
    #pragma unroll
    for (int q = 0; q < NPAR; ++q) {
        if (lv[q] > 0.f) {
            float wgt = ex2f(mv[q] - mmax);
            float4 v = *(const float4*)&g_Op[((size_t)q*SEQ + row)*DH + c];
            acc.x += wgt*v.x; acc.y += wgt*v.y; acc.z += wgt*v.z; acc.w += wgt*v.w;
            ws += wgt * lv[q];
        }
    }
    float inv = 1.0f / ws;
    *(float4*)&Out[(size_t)row*DH + c] =
        make_float4(acc.x*inv, acc.y*inv, acc.z*inv, acc.w*inv);
}

// =====================================================================
extern "C" void kernel_launch(void* const* d_in, const int* in_sizes, int n_in,
                              void* d_out, int out_size)
{
    (void)in_sizes; (void)n_in; (void)out_size;
    const float* X  = (const float*)d_in[0];
    const float* Wq = (const float*)d_in[1];
    const float* Wk = (const float*)d_in[2];
    const float* Wv = (const float*)d_in[3];

    const int nTot = SEQ*DM/4 + 3*DH*DM/4;
    split_all_kernel<<<(nTot + 255)/256, 256>>>(
        (const float4*)X, (const float4*)Wq, (const float4*)Wk, (const float4*)Wv);

    const int PSM = 2*PSSZ;                 // 92160 (2 CTAs/SM)
    cudaFuncSetAttribute(proj_kernel, cudaFuncAttributeMaxDynamicSharedMemorySize, PSM);
    cudaFuncSetAttribute(attn_kernel, cudaFuncAttributeMaxDynamicSharedMemorySize, ASM_T);

    proj_kernel<<<dim3(128, 3), 256, PSM>>>();
    attn_kernel<<<444, 128, ASM_T>>>();
    merge_kernel<<<SEQ/4, 128>>>((float*)d_out);
}

// round 15
// speedup vs baseline: 1.7897x; 1.0861x over previous
#include <cuda_runtime.h>
#include <cuda_fp16.h>
#include <cstdint>

typedef uint32_t u32;

#define SEQ 8192
#define DM  1024
#define DH  128
#define NPAR 6
#define NUNITS (128*NPAR)

#define NEGINF __int_as_float(0xff800000u)
#define ONESF  0x3C003C00u     // fp16x2 {1.0, 1.0} — B-fragment of all-ones matrix

// ---------------- device scratch (no allocs allowed) ----------------
__device__ __align__(16) __half g_Xh[SEQ*DM];
__device__ __align__(16) __half g_Wh[3*DH*DM], g_Wl[3*DH*DM];
__device__ __align__(16) __half g_Q[SEQ*DH];               // scaled by log2e/sqrt(dk)
__device__ __align__(16) __half g_K[SEQ*DH];
__device__ __align__(16) __half g_Vt[DH*SEQ];              // V transposed [dim][seq]
__device__ float g_Op[NPAR*SEQ*DH];
__device__ float g_mrow[NPAR*SEQ], g_lrow[NPAR*SEQ];
__device__ u32 g_ctr;                                      // persistent work counter

// ---------------- helpers ----------------
__device__ __forceinline__ u32 s2u(const void* p){
    u32 a; asm("{ .reg .u64 t; cvta.to.shared.u64 t, %1; cvt.u32.u64 %0, t; }" : "=r"(a) : "l"(p)); return a;
}
__device__ __forceinline__ void split2(float a, float b, u32 &h, u32 &l){
    __half2 hh = __floats2half2_rn(a, b);
    h = *reinterpret_cast<u32*>(&hh);
    float2 bk = __half22float2(hh);
    __half2 ll = __floats2half2_rn(a - bk.x, b - bk.y);
    l = *reinterpret_cast<u32*>(&ll);
}
__device__ __forceinline__ u32 packh2(float a, float b){
    __half2 hh = __floats2half2_rn(a, b);
    return *reinterpret_cast<u32*>(&hh);
}
__device__ __forceinline__ float ex2f(float x){
    float r; asm("ex2.approx.ftz.f32 %0, %1;" : "=f"(r) : "f"(x)); return r;
}
__device__ __forceinline__ void ldsm4(u32 a, u32 &r0, u32 &r1, u32 &r2, u32 &r3){
    asm volatile("ldmatrix.sync.aligned.m8n8.x4.shared.b16 {%0,%1,%2,%3}, [%4];"
        : "=r"(r0), "=r"(r1), "=r"(r2), "=r"(r3) : "r"(a));
}
__device__ __forceinline__ void mma16816(float* d, u32 a0, u32 a1, u32 a2, u32 a3, u32 b0, u32 b1){
    asm volatile("mma.sync.aligned.m16n8k16.row.col.f32.f16.f16.f32 "
        "{%0,%1,%2,%3},{%4,%5,%6,%7},{%8,%9},{%0,%1,%2,%3};"
        : "+f"(d[0]), "+f"(d[1]), "+f"(d[2]), "+f"(d[3])
        : "r"(a0), "r"(a1), "r"(a2), "r"(a3), "r"(b0), "r"(b1));
}
__device__ __forceinline__ void cpa16(u32 dst, const void* src){
    asm volatile("cp.async.cg.shared.global [%0], [%1], 16;" :: "r"(dst), "l"(src));
}
#define CPCOMMIT() asm volatile("cp.async.commit_group;" ::: "memory")
#define CPWAIT0()  asm volatile("cp.async.wait_group 0;" ::: "memory")

// =====================================================================
// Kernel 0: fp32 -> fp16 (X: hi only; W: split hi+lo) + counter reset
// =====================================================================
__global__ void split_all_kernel(const float4* __restrict__ X,
                                 const float4* __restrict__ Wq,
                                 const float4* __restrict__ Wk,
                                 const float4* __restrict__ Wv)
{
    if (blockIdx.x == 0 && threadIdx.x == 0) g_ctr = 0u;   // reset work queue
    const int nX4 = SEQ*DM/4, nW4 = DH*DM/4;
    int i = blockIdx.x * blockDim.x + threadIdx.x;
    if (i < nX4) {
        float4 v = X[i];
        ((uint2*)g_Xh)[i] = make_uint2(packh2(v.x, v.y), packh2(v.z, v.w));
        return;
    }
    int k = i - nX4;
    if (k >= 3*nW4) return;
    int mat = k / nW4; int off = k - mat*nW4;
    const float4* src = (mat==0) ? Wq : (mat==1) ? Wk : Wv;
    uint2* dh = (uint2*)(g_Wh + (size_t)mat*DH*DM);
    uint2* dl = (uint2*)(g_Wl + (size_t)mat*DH*DM);
    float4 v = src[off];
    u32 h0, l0, h1, l1;
    split2(v.x, v.y, h0, l0);
    split2(v.z, v.w, h1, l1);
    dh[off] = make_uint2(h0, h1);
    dl[off] = make_uint2(l0, l1);
}

// =====================================================================
// Kernel 1: QKV projection, 2-term fp16 (Xh·Wh + Xh·Wl), 2-stream acc,
// cp.async 2-stage, 2 CTAs/SM. grid(128,3): M-tile 64. 256 thr.
// =====================================================================
#define PSB   144
#define PXH   0
#define PWH   9216
#define PWL   27648
#define PSSZ  46080

__global__ void __launch_bounds__(256,2) proj_kernel()
{
    extern __shared__ __align__(16) char sm[];
    const u32 sb = s2u(sm);

    const int tid = threadIdx.x, lane = tid & 31, wid = tid >> 5;
    const int wm = wid >> 2, wn = wid & 3;       // 2m x 4n
    const int m0 = blockIdx.x * 64, mat = blockIdx.y;
    const __half* __restrict__ Wbh = g_Wh + (size_t)mat*DH*DM;
    const __half* __restrict__ Wbl = g_Wl + (size_t)mat*DH*DM;
    const float scale = (mat==0) ? 0.1275174436f : 1.0f;   // log2e/sqrt(128)

    const int aRow = lane & 15, aKB = (lane >> 4) << 3;
    const int bRow = (lane & 7) + ((lane >> 4) & 1) * 8, bKB = ((lane >> 3) & 1) << 3;

    auto issue = [&](int kc, int st){
        const u32 base = sb + st*PSSZ;
        #pragma unroll
        for (int it = 0; it < 2; ++it) {
            int idx = tid + it*256;
            int r = idx >> 3, c = idx & 7;
            cpa16(base + PXH + r*PSB + c*16, &g_Xh[(size_t)(m0 + r)*DM + kc*64 + c*8]);
        }
        #pragma unroll
        for (int it = 0; it < 4; ++it) {
            int idx = tid + it*256;
            int r = idx >> 3, c = idx & 7;
            cpa16(base + PWH + r*PSB + c*16, &Wbh[(size_t)r*DM + kc*64 + c*8]);
            cpa16(base + PWL + r*PSB + c*16, &Wbl[(size_t)r*DM + kc*64 + c*8]);
        }
        CPCOMMIT();
    };

    float a1[2][4][4], a2[2][4][4];
    #pragma unroll
    for (int i = 0; i < 2; ++i)
        #pragma unroll
        for (int j = 0; j < 4; ++j)
            #pragma unroll
            for (int c = 0; c < 4; ++c) { a1[i][j][c] = 0.f; a2[i][j][c] = 0.f; }

    issue(0, 0);
    for (int kc = 0; kc < 16; ++kc) {
        const int st = kc & 1;
        const u32 base = sb + st*PSSZ;
        CPWAIT0();
        __syncthreads();
        if (kc + 1 < 16) issue(kc + 1, st ^ 1);

        #pragma unroll
        for (int ks = 0; ks < 4; ++ks) {
            u32 ah[2][4];
            #pragma unroll
            for (int mt = 0; mt < 2; ++mt) {
                u32 qa = base + PXH + (u32)((wm*32 + mt*16 + aRow)*PSB + (ks*16 + aKB)*2);
                ldsm4(qa, ah[mt][0], ah[mt][1], ah[mt][2], ah[mt][3]);
            }
            #pragma unroll
            for (int nb = 0; nb < 2; ++nb) {
                u32 bh[4], bl[4];
                u32 ba = base + PWH + (u32)((wn*32 + nb*16 + bRow)*PSB + (ks*16 + bKB)*2);
                ldsm4(ba,             bh[0], bh[1], bh[2], bh[3]);
                ldsm4(ba + (PWL-PWH), bl[0], bl[1], bl[2], bl[3]);
                #pragma unroll
                for (int mt = 0; mt < 2; ++mt) {
                    mma16816(a1[mt][nb*2],   ah[mt][0],ah[mt][1],ah[mt][2],ah[mt][3], bh[0], bh[1]);
                    mma16816(a2[mt][nb*2],   ah[mt][0],ah[mt][1],ah[mt][2],ah[mt][3], bl[0], bl[1]);
                    mma16816(a1[mt][nb*2+1], ah[mt][0],ah[mt][1],ah[mt][2],ah[mt][3], bh[2], bh[3]);
                    mma16816(a2[mt][nb*2+1], ah[mt][0],ah[mt][1],ah[mt][2],ah[mt][3], bl[2], bl[3]);
                }
            }
        }
        __syncthreads();
    }

    #pragma unroll
    for (int mt = 0; mt < 2; ++mt) {
        const int r0 = m0 + wm*32 + mt*16 + (lane >> 2);
        const int r1 = r0 + 8;
        #pragma unroll
        for (int nt = 0; nt < 4; ++nt) {
            const int col = wn*32 + nt*8 + (lane & 3)*2;
            float c0 = (a1[mt][nt][0] + a2[mt][nt][0])*scale;
            float c1 = (a1[mt][nt][1] + a2[mt][nt][1])*scale;
            float c2 = (a1[mt][nt][2] + a2[mt][nt][2])*scale;
            float c3 = (a1[mt][nt][3] + a2[mt][nt][3])*scale;
            if (mat < 2) {
                __half* G = (mat==0) ? g_Q : g_K;
                *(u32*)&G[(size_t)r0*DH + col] = packh2(c0, c1);
                *(u32*)&G[(size_t)r1*DH + col] = packh2(c2, c3);
            } else {
                g_Vt[(size_t)(col    )*SEQ + r0] = __float2half_rn(c0);
                g_Vt[(size_t)(col + 1)*SEQ + r0] = __float2half_rn(c1);
                g_Vt[(size_t)(col    )*SEQ + r1] = __float2half_rn(c2);
                g_Vt[(size_t)(col + 1)*SEQ + r1] = __float2half_rn(c3);
            }
        }
    }
}

// =====================================================================
// Kernel 2: causal flash attention, all-fp16, log2-domain softmax,
// l via constant all-ones B-fragment PV-MMA. Persistent 444 CTAs,
// LPT work queue. NEW: V double-buffered + phase-shifted {K,V}(j+1)
// prefetch issued after the post-S barrier -> load latency hidden
// under softmax+PV. 3 CTAs/SM (71.7KB smem each).
// =====================================================================
#define ASB   272            // Q/K row stride bytes
#define VSB   144            // V row stride bytes
#define AQ    0              // Q: 64 x 272 = 17408
#define AK    17408          // K: 64 x 272 = 17408
#define AV0   34816          // V buf0: 128 x 144 = 18432
#define AV1   53248          // V buf1: 128 x 144 = 18432
#define ASM_T 71680

__global__ void __launch_bounds__(128,3) attn_kernel()
{
    extern __shared__ __align__(16) char sm[];
    __shared__ u32 s_unit;
    const u32 sb = s2u(sm);

    const int tid = threadIdx.x, lane = tid & 31, w = tid >> 5;

    const int aRow = lane & 15, aKB = (lane >> 4) << 3;
    const int bRow = (lane & 7) + ((lane >> 4) & 1) * 8, bKB = ((lane >> 3) & 1) << 3;
    const int rl0 = w*16 + (lane >> 2);   // local q-row (0..63)
    const int rl1 = rl0 + 8;

    // issue K(j) into AK and V(j) into buffer j&1, one commit group
    auto issueKV = [&](int j){
        #pragma unroll
        for (int it = 0; it < 8; ++it) {     // K: 64 rows x 16 chunks
            int idx = tid + it*128;
            int r = idx >> 4, c = idx & 15;
            cpa16(sb + AK + r*ASB + c*16, &g_K[(size_t)(j*64 + r)*DH + c*8]);
        }
        const u32 vb = sb + ((j & 1) ? AV1 : AV0);
        #pragma unroll
        for (int it = 0; it < 8; ++it) {     // V: 128 dim-rows x 8 chunks
            int idx = tid + it*128;
            int r = idx >> 3, c = idx & 7;
            cpa16(vb + r*VSB + c*16, &g_Vt[(size_t)r*SEQ + j*64 + c*8]);
        }
        CPCOMMIT();
    };

    #pragma unroll 1
    while (true) {
        __syncthreads();   // prior unit done with smem + s_unit
        if (tid == 0) s_unit = atomicAdd(&g_ctr, 1u);
        __syncthreads();
        const u32 u = s_unit;
        if (u >= (u32)NUNITS) break;

        const int i  = 127 - (int)(u / NPAR);   // big tiles first (LPT)
        const int qq = (int)(u % NPAR);
        const int Tt = i + 1;                   // 64-key subtiles
        const int Tq = (Tt + NPAR - 1) / NPAR;
        const int j0 = qq * Tq;
        const int j1 = (j0 + Tq < Tt) ? (j0 + Tq) : Tt;
        const int brow = qq*SEQ + i*64;

        if (j0 >= j1) {
            if (tid < 64) { g_mrow[brow + tid] = NEGINF; g_lrow[brow + tid] = 0.f; }
            continue;
        }

        // prologue: Q + K(j0) + V(j0) in one commit group
        #pragma unroll
        for (int it = 0; it < 8; ++it) {
            int idx = tid + it*128;
            int r = idx >> 4, c = idx & 15;
            cpa16(sb + AQ + r*ASB + c*16, &g_Q[(size_t)(i*64 + r)*DH + c*8]);
        }
        issueKV(j0);

        float o[16][4], ol[4];
        #pragma unroll
        for (int nt = 0; nt < 16; ++nt)
            #pragma unroll
            for (int c = 0; c < 4; ++c) o[nt][c] = 0.f;
        #pragma unroll
        for (int c = 0; c < 4; ++c) ol[c] = 0.f;
        float m0r = NEGINF, m1r = NEGINF;

        #pragma unroll 1
        for (int j = j0; j < j1; ++j) {
            CPWAIT0();                     // {K(j), V(j)} (+Q first time) landed
            __syncthreads();               // visible to all warps

            // ---- S = Q K^T, single fp16 term ----
            float s[8][4];
            #pragma unroll
            for (int nt = 0; nt < 8; ++nt)
                #pragma unroll
                for (int c = 0; c < 4; ++c) s[nt][c] = 0.f;

            #pragma unroll
            for (int ks = 0; ks < 8; ++ks) {
                u32 qf[4];
                u32 qa = sb + AQ + (u32)((w*16 + aRow)*ASB + (ks*16 + aKB)*2);
                ldsm4(qa, qf[0], qf[1], qf[2], qf[3]);
                #pragma unroll
                for (int nbp = 0; nbp < 4; ++nbp) {
                    u32 kf[4];
                    u32 ba = sb + AK + (u32)((nbp*16 + bRow)*ASB + (ks*16 + bKB)*2);
                    ldsm4(ba, kf[0], kf[1], kf[2], kf[3]);
                    mma16816(s[nbp*2],   qf[0],qf[1],qf[2],qf[3], kf[0], kf[1]);
                    mma16816(s[nbp*2+1], qf[0],qf[1],qf[2],qf[3], kf[2], kf[3]);
                }
            }
            __syncthreads();               // all warps done reading K(j)
            if (j + 1 < j1) issueKV(j + 1);   // prefetch hidden under softmax+PV

            // ---- causal mask (diagonal subtile only) ----
            if (j == i) {
                const int gr0 = i*64 + rl0, gr1 = i*64 + rl1;
                #pragma unroll
                for (int nt = 0; nt < 8; ++nt) {
                    int gc = j*64 + nt*8 + (lane & 3)*2;
                    if (gc     > gr0) s[nt][0] = NEGINF;
                    if (gc + 1 > gr0) s[nt][1] = NEGINF;
                    if (gc     > gr1) s[nt][2] = NEGINF;
                    if (gc + 1 > gr1) s[nt][3] = NEGINF;
                }
            }

            // ---- online softmax (log2 domain, quad-local rows) ----
            float mx0 = NEGINF, mx1 = NEGINF;
            #pragma unroll
            for (int nt = 0; nt < 8; ++nt) {
                mx0 = fmaxf(mx0, fmaxf(s[nt][0], s[nt][1]));
                mx1 = fmaxf(mx1, fmaxf(s[nt][2], s[nt][3]));
            }
            mx0 = fmaxf(mx0, __shfl_xor_sync(0xffffffffu, mx0, 1));
            mx0 = fmaxf(mx0, __shfl_xor_sync(0xffffffffu, mx0, 2));
            mx1 = fmaxf(mx1, __shfl_xor_sync(0xffffffffu, mx1, 1));
            mx1 = fmaxf(mx1, __shfl_xor_sync(0xffffffffu, mx1, 2));

            float mn0 = fmaxf(m0r, mx0), mn1 = fmaxf(m1r, mx1);
            float al0 = ex2f(m0r - mn0), al1 = ex2f(m1r - mn1);
            m0r = mn0;  m1r = mn1;

            u32 p2[16];
            #pragma unroll
            for (int nt = 0; nt < 8; ++nt) {
                float p0  = ex2f(s[nt][0] - mn0);
                float p1  = ex2f(s[nt][1] - mn0);
                float p2f = ex2f(s[nt][2] - mn1);
                float p3  = ex2f(s[nt][3] - mn1);
                p2[nt*2]   = packh2(p0, p1);
                p2[nt*2+1] = packh2(p2f, p3);
            }

            bool need = (al0 < 1.f) || (al1 < 1.f);
            if (__ballot_sync(0xffffffffu, need)) {
                #pragma unroll
                for (int nt = 0; nt < 16; ++nt) {
                    o[nt][0] *= al0;  o[nt][1] *= al0;
                    o[nt][2] *= al1;  o[nt][3] *= al1;
                }
                ol[0] *= al0; ol[1] *= al0; ol[2] *= al1; ol[3] *= al1;
            }

            // ---- O += P * V[j&1] ; l += P * ones (constant fragment) ----
            const u32 vb = sb + ((j & 1) ? AV1 : AV0);
            #pragma unroll
            for (int t = 0; t < 4; ++t) {
                mma16816(ol, p2[4*t],p2[4*t+1],p2[4*t+2],p2[4*t+3], ONESF, ONESF);
                #pragma unroll
                for (int nbp = 0; nbp < 8; ++nbp) {
                    u32 vh[4];
                    u32 ba = vb + (u32)((nbp*16 + bRow)*VSB + (t*16 + bKB)*2);
                    ldsm4(ba, vh[0], vh[1], vh[2], vh[3]);
                    mma16816(o[nbp*2],   p2[4*t],p2[4*t+1],p2[4*t+2],p2[4*t+3], vh[0], vh[1]);
                    mma16816(o[nbp*2+1], p2[4*t],p2[4*t+1],p2[4*t+2],p2[4*t+3], vh[2], vh[3]);
                }
            }
            // no barrier here: next loop-top CPWAIT0+sync orders everything
        }

        // ---- store partials (l from the ones-fragment MMA) ----
        const int gr0 = brow + rl0, gr1 = brow + rl1;
        #pragma unroll
        for (int nt = 0; nt < 16; ++nt) {
            const int col = nt*8 + (lane & 3)*2;
            *(float2*)&g_Op[(size_t)gr0*DH + col] = make_float2(o[nt][0], o[nt][1]);
            *(float2*)&g_Op[(size_t)gr1*DH + col] = make_float2(o[nt][2], o[nt][3]);
        }
        if ((lane & 3) == 0) {
            g_mrow[gr0] = m0r;  g_lrow[gr0] = ol[0];
            g_mrow[gr1] = m1r;  g_lrow[gr1] = ol[2];
        }
    }
}

// =====================================================================
// Kernel 3: merge NPAR partials per row (LSE combine, log2 domain).
// =====================================================================
__global__ void merge_kernel(float* __restrict__ Out)
{
    const int t = threadIdx.x;
    const int row = blockIdx.x*4 + (t >> 5);
    const int c = (t & 31)*4;

    float mv[NPAR], lv[NPAR];
    float mmax = NEGINF;
    #pragma unroll
    for (int q = 0; q < NPAR; ++q) {
        mv[q] = g_mrow[q*SEQ + row];
        lv[q] = g_lrow[q*SEQ + row];
        if (lv[q] > 0.f) mmax = fmaxf(mmax, mv[q]);
    }
    float4 acc = make_float4(0.f, 0.f, 0.f, 0.f);
    float ws = 0.f;
    #pragma unroll
    for (int q = 0; q < NPAR; ++q) {
        if (lv[q] > 0.f) {
            float wgt = ex2f(mv[q] - mmax);
            float4 v = *(const float4*)&g_Op[((size_t)q*SEQ + row)*DH + c];
            acc.x += wgt*v.x; acc.y += wgt*v.y; acc.z += wgt*v.z; acc.w += wgt*v.w;
            ws += wgt * lv[q];
        }
    }
    float inv = 1.0f / ws;
    *(float4*)&Out[(size_t)row*DH + c] =
        make_float4(acc.x*inv, acc.y*inv, acc.z*inv, acc.w*inv);
}

// =====================================================================
extern "C" void kernel_launch(void* const* d_in, const int* in_sizes, int n_in,
                              void* d_out, int out_size)
{
    (void)in_sizes; (void)n_in; (void)out_size;
    const float* X  = (const float*)d_in[0];
    const float* Wq = (const float*)d_in[1];
    const float* Wk = (const float*)d_in[2];
    const float* Wv = (const float*)d_in[3];

    const int nTot = SEQ*DM/4 + 3*DH*DM/4;
    split_all_kernel<<<(nTot + 255)/256, 256>>>(
        (const float4*)X, (const float4*)Wq, (const float4*)Wk, (const float4*)Wv);

    const int PSM = 2*PSSZ;                 // 92160 (2 CTAs/SM)
    cudaFuncSetAttribute(proj_kernel, cudaFuncAttributeMaxDynamicSharedMemorySize, PSM);
    cudaFuncSetAttribute(attn_kernel, cudaFuncAttributeMaxDynamicSharedMemorySize, ASM_T);

    proj_kernel<<<dim3(128, 3), 256, PSM>>>();
    attn_kernel<<<444, 128, ASM_T>>>();
    merge_kernel<<<SEQ/4, 128>>>((float*)d_out);
}